// round 9
// baseline (speedup 1.0000x reference)
#include <cuda_runtime.h>
#include <cuda_bf16.h>
#include <cstdint>

#define BATCH 32
#define CH    2048
#define NHW   576
#define MID   256

typedef unsigned long long u64;
typedef uint32_t u32;

// ------------------------- scratch (device globals) -------------------------
__device__ float g_attn[(size_t)BATCH * NHW * NHW];
__device__ __nv_bfloat16 g_cam_h[(size_t)BATCH * CH * NHW];
__device__ __nv_bfloat16 g_cam_l[(size_t)BATCH * CH * NHW];
__device__ __nv_bfloat16 g_feat_h[(size_t)BATCH * CH * NHW];
__device__ __nv_bfloat16 g_feat_l[(size_t)BATCH * CH * NHW];
__device__ __nv_bfloat16 g_attn_h[(size_t)BATCH * NHW * NHW];
__device__ __nv_bfloat16 g_attn_l[(size_t)BATCH * NHW * NHW];
__device__ __nv_bfloat16 g_Wh[512 * 2048];   // rows 0-255: W1, 256-511: W2
__device__ __nv_bfloat16 g_Wl[512 * 2048];
__device__ __nv_bfloat16 g_f1t_h[(size_t)BATCH * NHW * MID];
__device__ __nv_bfloat16 g_f1t_l[(size_t)BATCH * NHW * MID];
__device__ __nv_bfloat16 g_f2t_h[(size_t)BATCH * NHW * MID];
__device__ __nv_bfloat16 g_f2t_l[(size_t)BATCH * NHW * MID];

// ------------------------- helpers -------------------------
__device__ __forceinline__ u32 smem_u32(const void* p) {
    u32 a;
    asm("{ .reg .u64 t; cvta.to.shared.u64 t, %1; cvt.u32.u64 %0, t; }" : "=r"(a) : "l"(p));
    return a;
}
__device__ __forceinline__ u64 gaddr(const void* p) {
    u64 a; asm("cvta.to.global.u64 %0, %1;" : "=l"(a) : "l"(p)); return a;
}
__device__ __forceinline__ void cp16(u32 s, u64 g) {
    asm volatile("cp.async.cg.shared.global [%0], [%1], 16;" :: "r"(s), "l"(g) : "memory");
}
#define CP_COMMIT() asm volatile("cp.async.commit_group;" ::: "memory")
#define CP_WAIT(n)  asm volatile("cp.async.wait_group %0;" :: "n"(n) : "memory")

__device__ __forceinline__ void ldm_x4(u32* r, u32 a) {
    asm volatile("ldmatrix.sync.aligned.m8n8.x4.shared.b16 {%0,%1,%2,%3}, [%4];"
        : "=r"(r[0]), "=r"(r[1]), "=r"(r[2]), "=r"(r[3]) : "r"(a));
}
__device__ __forceinline__ void ldm_x2(u32* r, u32 a) {
    asm volatile("ldmatrix.sync.aligned.m8n8.x2.shared.b16 {%0,%1}, [%2];"
        : "=r"(r[0]), "=r"(r[1]) : "r"(a));
}
__device__ __forceinline__ void ldm_x2t(u32* r, u32 a) {
    asm volatile("ldmatrix.sync.aligned.m8n8.x2.trans.shared.b16 {%0,%1}, [%2];"
        : "=r"(r[0]), "=r"(r[1]) : "r"(a));
}
__device__ __forceinline__ void mma_bf16(float* d, const u32* a, const u32* b) {
    asm volatile(
        "mma.sync.aligned.m16n8k16.row.col.f32.bf16.bf16.f32 "
        "{%0,%1,%2,%3}, {%4,%5,%6,%7}, {%8,%9}, {%0,%1,%2,%3};"
        : "+f"(d[0]), "+f"(d[1]), "+f"(d[2]), "+f"(d[3])
        : "r"(a[0]), "r"(a[1]), "r"(a[2]), "r"(a[3]), "r"(b[0]), "r"(b[1]));
}

extern __shared__ __align__(16) char dsm[];

// ---------------------------------------------------------------------------
// Converters: fp32 -> (hi, lo) bf16 pair.
// ---------------------------------------------------------------------------
__device__ __forceinline__ void split4(float4 v, __nv_bfloat16* h, __nv_bfloat16* l, size_t i) {
    __nv_bfloat16 h0 = __float2bfloat16_rn(v.x), h1 = __float2bfloat16_rn(v.y);
    __nv_bfloat16 h2 = __float2bfloat16_rn(v.z), h3 = __float2bfloat16_rn(v.w);
    __nv_bfloat16 l0 = __float2bfloat16_rn(v.x - __bfloat162float(h0));
    __nv_bfloat16 l1 = __float2bfloat16_rn(v.y - __bfloat162float(h1));
    __nv_bfloat16 l2 = __float2bfloat16_rn(v.z - __bfloat162float(h2));
    __nv_bfloat16 l3 = __float2bfloat16_rn(v.w - __bfloat162float(h3));
    *(__nv_bfloat162*)(h + i)     = __nv_bfloat162(h0, h1);
    *(__nv_bfloat162*)(h + i + 2) = __nv_bfloat162(h2, h3);
    *(__nv_bfloat162*)(l + i)     = __nv_bfloat162(l0, l1);
    *(__nv_bfloat162*)(l + i + 2) = __nv_bfloat162(l2, l3);
}

__global__ __launch_bounds__(256) void k_cvt_cam(const float* __restrict__ src) {
    size_t i = ((size_t)blockIdx.x * 256 + threadIdx.x) * 4;
    split4(*(const float4*)(src + i), g_cam_h, g_cam_l, i);
}
__global__ __launch_bounds__(256) void k_cvt_feat(const float* __restrict__ src) {
    size_t i = ((size_t)blockIdx.x * 256 + threadIdx.x) * 4;
    split4(*(const float4*)(src + i), g_feat_h, g_feat_l, i);
}
__global__ __launch_bounds__(256) void k_cvt_w(const float* __restrict__ W1,
                                               const float* __restrict__ W2) {
    size_t i = ((size_t)blockIdx.x * 256 + threadIdx.x) * 4;
    const float* src = (i < (size_t)256 * 2048) ? (W1 + i) : (W2 + i - (size_t)256 * 2048);
    split4(*(const float4*)src, g_Wh, g_Wl, i);
}

// ---------------------------------------------------------------------------
// k_conv_mma: [f1; f2] = [W1;W2](512x2048) @ feat(2048x576), 3-term bf16 split.
// NEW tiles: BM=256 (full W1 or W2), BN=64. 8 warps = 4 wm (64 rows) x 2 wn (32 cols).
// K-chunk 32, 2-stage, one barrier per iter.
// stage: Ah 256x80B (20480) | Al (20480) | Bh 32x144B (4608) | Bl (4608) = 50176
// Epilogue: smem transpose -> f{1,2}t[n][0..255] full rows.
// ---------------------------------------------------------------------------
#define KC_STAGE 50176

__global__ __launch_bounds__(256) void k_conv_mma() {
    const int tid = threadIdx.x, wid = tid >> 5, l = tid & 31;
    const int b = blockIdx.z, m0 = blockIdx.y * 256, n0 = blockIdx.x * 64;
    const int wm = wid & 3, wn = wid >> 2;
    const u32 smb = smem_u32(dsm);

    const u64 gWh = gaddr(g_Wh), gWl = gaddr(g_Wl);
    const u64 gFh = gaddr(g_feat_h), gFl = gaddr(g_feat_l);

    float acc[4][4][4] = {};

    auto load_tiles = [&](int k0, u32 st) {
        #pragma unroll
        for (int t = 0; t < 10; ++t) {
            const int idx = tid + 256 * t;   // 0..2559
            if (idx < 2048) {
                const int layer = idx >> 10;
                const int a = idx & 1023, r = a >> 2, c = a & 3;
                const u64 g = (layer ? gWl : gWh) +
                    ((u64)(m0 + r) * 2048 + (u32)(k0 + c * 8)) * 2;
                cp16(st + (u32)layer * 20480u + (u32)r * 80 + (u32)c * 16, g);
            } else {
                const int j = idx - 2048;        // 0..511
                const int layer = j >> 8;
                const int j2 = j & 255;
                const int r = j2 >> 3, c = j2 & 7;
                const u64 g = (layer ? gFl : gFh) +
                    ((u64)(b * CH + k0 + r) * NHW + (u32)(n0 + c * 8)) * 2;
                cp16(st + 40960u + (u32)layer * 4608u + (u32)r * 144 + (u32)c * 16, g);
            }
        }
    };

    load_tiles(0, smb);
    CP_COMMIT();

    const u32 a_base = (u32)(wm * 64 + (l & 7) + ((l >> 3) & 1) * 8) * 80 + ((l >> 4) & 1) * 16;
    const int lb = l & 15;
    const u32 b_base = (u32)((lb & 7) + ((lb >> 3) & 1) * 8) * 144 + (u32)(wn * 32) * 2;

    for (int it = 0; it < 64; ++it) {
        CP_WAIT(0);
        __syncthreads();
        if (it + 1 < 64) {
            load_tiles((it + 1) * 32, smb + (u32)((it + 1) & 1) * KC_STAGE);
            CP_COMMIT();
        }
        const u32 st = smb + (u32)(it & 1) * KC_STAGE;

        #pragma unroll
        for (int k16 = 0; k16 < 2; ++k16) {
            u32 ah[4][4], al[4][4];
            #pragma unroll
            for (int mb = 0; mb < 4; ++mb) {
                ldm_x4(ah[mb], st + a_base + (u32)mb * 1280 + (u32)k16 * 32);
                ldm_x4(al[mb], st + 20480u + a_base + (u32)mb * 1280 + (u32)k16 * 32);
            }
            #pragma unroll
            for (int nb = 0; nb < 4; ++nb) {
                u32 bh[2], bl[2];
                const u32 ba = st + 40960u + b_base + (u32)k16 * 2304 + (u32)nb * 16;
                ldm_x2t(bh, ba);
                ldm_x2t(bl, ba + 4608u);
                #pragma unroll
                for (int mb = 0; mb < 4; ++mb) {
                    mma_bf16(acc[mb][nb], ah[mb], bh);
                    mma_bf16(acc[mb][nb], ah[mb], bl);
                    mma_bf16(acc[mb][nb], al[mb], bh);
                }
            }
        }
    }
    __syncthreads();

    // --- epilogue: smem transpose -> split bf16, write f{1,2}t[n][0..255] ---
    // Th: [64 n][256 m] bf16 (512B rows) at dsm+0; Tl at dsm+32768.
    const int g = l >> 2, t2 = (l & 3) * 2;
    #pragma unroll
    for (int mb = 0; mb < 4; ++mb) {
        #pragma unroll
        for (int nb = 0; nb < 4; ++nb) {
            const int ml = wm * 64 + mb * 16 + g;
            const int nl = wn * 32 + nb * 8 + t2;
            #pragma unroll
            for (int q = 0; q < 4; ++q) {
                const float v = acc[mb][nb][q];
                const int m_ = ml + (q >> 1) * 8;
                const int n_ = nl + (q & 1);
                __nv_bfloat16 h = __float2bfloat16_rn(v);
                __nv_bfloat16 lo = __float2bfloat16_rn(v - __bfloat162float(h));
                *(__nv_bfloat16*)(dsm + (u32)n_ * 512 + (u32)m_ * 2) = h;
                *(__nv_bfloat16*)(dsm + 32768u + (u32)n_ * 512 + (u32)m_ * 2) = lo;
            }
        }
    }
    __syncthreads();

    __nv_bfloat16* dh = (m0 == 0) ? g_f1t_h : g_f2t_h;
    __nv_bfloat16* dl = (m0 == 0) ? g_f1t_l : g_f2t_l;
    #pragma unroll
    for (int t = 0; t < 8; ++t) {
        const int idx = tid + 256 * t;   // 0..2047
        const int j = idx >> 5, c = idx & 31;
        const size_t off = ((size_t)b * NHW + n0 + j) * MID + c * 8;
        *(uint4*)(dh + off) = *(const uint4*)(dsm + (u32)j * 512 + (u32)c * 16);
        *(uint4*)(dl + off) = *(const uint4*)(dsm + 32768u + (u32)j * 512 + (u32)c * 16);
    }
}

// ---------------------------------------------------------------------------
// k_logits_mma: logits[i][j] = sum_m f1t[i][m]*f2t[j][m]. K=256, 3-term split.
// BM=BN=96, K-chunk 32, 2-stage, one barrier per iter.
// ---------------------------------------------------------------------------
#define KL_STAGE 30720

__global__ __launch_bounds__(256) void k_logits_mma() {
    const int tid = threadIdx.x, wid = tid >> 5, l = tid & 31;
    const int b = blockIdx.z, i0 = blockIdx.y * 96, j0 = blockIdx.x * 96;
    const int wm = wid & 1, wn = wid >> 1;
    const u32 smb = smem_u32(dsm);

    const u64 g1h = gaddr(g_f1t_h), g1l = gaddr(g_f1t_l);
    const u64 g2h = gaddr(g_f2t_h), g2l = gaddr(g_f2t_l);

    float acc[3][3][4] = {};

    auto load_tiles = [&](int k0, u32 st) {
        #pragma unroll
        for (int t = 0; t < 6; ++t) {
            const int idx = tid + 256 * t;
            const int side = idx >= 768;
            const int i2 = idx - (side ? 768 : 0);
            const int half = i2 >= 384;
            const int j2 = i2 - (half ? 384 : 0);
            const int r = j2 >> 2, c = j2 & 3;
            const u64 src = (side ? (half ? g2l : g2h) : (half ? g1l : g1h)) +
                ((u64)(b * NHW + (side ? j0 : i0) + r) * MID + (u32)(k0 + c * 8)) * 2;
            cp16(st + (side ? 15360u : 0u) + (half ? 7680u : 0u) + (u32)r * 80 + (u32)c * 16, src);
        }
    };

    load_tiles(0, smb);
    CP_COMMIT();

    const u32 a_base = (u32)(wm * 48 + (l & 7) + ((l >> 3) & 1) * 8) * 80 + ((l >> 4) & 1) * 16;
    const int lb = l & 15;
    const u32 b_base = (u32)(wn * 24 + (lb & 7)) * 80 + (u32)((lb >> 3) & 1) * 16;

    for (int it = 0; it < 8; ++it) {
        CP_WAIT(0);
        __syncthreads();
        if (it + 1 < 8) {
            load_tiles((it + 1) * 32, smb + (u32)((it + 1) & 1) * KL_STAGE);
            CP_COMMIT();
        }
        const u32 st = smb + (u32)(it & 1) * KL_STAGE;

        #pragma unroll
        for (int k16 = 0; k16 < 2; ++k16) {
            u32 ah[3][4], al[3][4];
            #pragma unroll
            for (int mb = 0; mb < 3; ++mb) {
                ldm_x4(ah[mb], st + a_base + (u32)mb * 1280 + (u32)k16 * 32);
                ldm_x4(al[mb], st + 7680u + a_base + (u32)mb * 1280 + (u32)k16 * 32);
            }
            #pragma unroll
            for (int nb = 0; nb < 3; ++nb) {
                u32 bh[2], bl[2];
                const u32 ba = st + 15360u + b_base + (u32)nb * 640 + (u32)k16 * 32;
                ldm_x2(bh, ba);
                ldm_x2(bl, ba + 7680u);
                #pragma unroll
                for (int mb = 0; mb < 3; ++mb) {
                    mma_bf16(acc[mb][nb], ah[mb], bh);
                    mma_bf16(acc[mb][nb], ah[mb], bl);
                    mma_bf16(acc[mb][nb], al[mb], bh);
                }
            }
        }
    }

    float* ab = g_attn + (size_t)b * NHW * NHW;
    const int g = l >> 2, t2 = (l & 3) * 2;
    #pragma unroll
    for (int mb = 0; mb < 3; ++mb) {
        #pragma unroll
        for (int nb = 0; nb < 3; ++nb) {
            const int row = i0 + wm * 48 + mb * 16 + g;
            const int col = j0 + wn * 24 + nb * 8 + t2;
            const size_t o = (size_t)row * NHW + col;
            *(float2*)(ab + o)           = make_float2(acc[mb][nb][0], acc[mb][nb][1]);
            *(float2*)(ab + o + 8 * NHW) = make_float2(acc[mb][nb][2], acc[mb][nb][3]);
        }
    }
}

// ---------------------------------------------------------------------------
// k_softmax: warp-per-row (576 elems, 18/lane), 8 rows per 256-thread block.
// ---------------------------------------------------------------------------
__global__ __launch_bounds__(256) void k_softmax() {
    const int wid = threadIdx.x >> 5, l = threadIdx.x & 31;
    const size_t row = (size_t)blockIdx.x * 8 + wid;
    const float* p = g_attn + row * NHW;
    __nv_bfloat16* oh = g_attn_h + row * NHW;
    __nv_bfloat16* ol = g_attn_l + row * NHW;

    float v[18];
    float m = -1e30f;
    #pragma unroll
    for (int i = 0; i < 18; ++i) { v[i] = p[l + 32 * i]; m = fmaxf(m, v[i]); }
    #pragma unroll
    for (int o = 16; o > 0; o >>= 1) m = fmaxf(m, __shfl_xor_sync(0xffffffffu, m, o));

    float s = 0.f;
    #pragma unroll
    for (int i = 0; i < 18; ++i) { v[i] = __expf(v[i] - m); s += v[i]; }
    #pragma unroll
    for (int o = 16; o > 0; o >>= 1) s += __shfl_xor_sync(0xffffffffu, s, o);

    const float inv = 1.0f / s;
    #pragma unroll
    for (int i = 0; i < 18; ++i) {
        float pv = v[i] * inv;
        __nv_bfloat16 h = __float2bfloat16_rn(pv);
        __nv_bfloat16 lo = __float2bfloat16_rn(pv - __bfloat162float(h));
        oh[l + 32 * i] = h;
        ol[l + 32 * i] = lo;
    }
}

// ---------------------------------------------------------------------------
// k_out_mma: out[c][n] = cam[c][n] + alpha * sum_k cam[c][k]*attn[n][k]
// BM=128, BN=96, K-chunk 32, 2-stage, one barrier per iter.
// ---------------------------------------------------------------------------
#define KO_STAGE 35840

__global__ __launch_bounds__(256) void k_out_mma(const float* __restrict__ cam,
                                                 const float* __restrict__ alpha_p,
                                                 float* __restrict__ out) {
    const int tid = threadIdx.x, wid = tid >> 5, l = tid & 31;
    const int b = blockIdx.z, c0 = blockIdx.y * 128, n0 = blockIdx.x * 96;
    const int wm = wid & 1, wn = wid >> 1;
    const u32 smb = smem_u32(dsm);

    const u64 gCh = gaddr(g_cam_h), gCl = gaddr(g_cam_l);
    const u64 gAh = gaddr(g_attn_h), gAl = gaddr(g_attn_l);

    float acc[4][3][4] = {};

    auto load_tiles = [&](int k0, u32 st) {
        #pragma unroll
        for (int t = 0; t < 7; ++t) {
            const int idx = tid + 256 * t;
            if (idx < 1024) {
                const int a = idx & 511, r = a >> 2, c = a & 3;
                const u64 g = ((idx < 512) ? gCh : gCl) +
                    ((u64)(b * CH + c0 + r) * NHW + (u32)(k0 + c * 8)) * 2;
                cp16(st + ((idx < 512) ? 0u : 10240u) + (u32)r * 80 + (u32)c * 16, g);
            } else {
                const int j = idx - 1024;
                const int half = j >= 384;
                const int j2 = j - (half ? 384 : 0);
                const int r = j2 >> 2, c = j2 & 3;
                const u64 g = (half ? gAl : gAh) +
                    ((u64)(b * NHW + n0 + r) * NHW + (u32)(k0 + c * 8)) * 2;
                cp16(st + 20480u + (half ? 7680u : 0u) + (u32)r * 80 + (u32)c * 16, g);
            }
        }
    };

    load_tiles(0, smb);
    CP_COMMIT();

    const u32 a_base = (u32)(wm * 64 + (l & 7) + ((l >> 3) & 1) * 8) * 80 + ((l >> 4) & 1) * 16;
    const int lb = l & 15;
    const u32 b_base = (u32)(wn * 24 + (lb & 7)) * 80 + (u32)((lb >> 3) & 1) * 16;

    for (int it = 0; it < 18; ++it) {
        CP_WAIT(0);
        __syncthreads();
        if (it + 1 < 18) {
            load_tiles((it + 1) * 32, smb + (u32)((it + 1) & 1) * KO_STAGE);
            CP_COMMIT();
        }
        const u32 st = smb + (u32)(it & 1) * KO_STAGE;

        #pragma unroll
        for (int k16 = 0; k16 < 2; ++k16) {
            u32 ah[4][4], al[4][4];
            #pragma unroll
            for (int mb = 0; mb < 4; ++mb) {
                ldm_x4(ah[mb], st + a_base + (u32)mb * 1280 + (u32)k16 * 32);
                ldm_x4(al[mb], st + 10240u + a_base + (u32)mb * 1280 + (u32)k16 * 32);
            }
            #pragma unroll
            for (int nb = 0; nb < 3; ++nb) {
                u32 bh[2], bl[2];
                const u32 ba = st + 20480u + b_base + (u32)nb * 640 + (u32)k16 * 32;
                ldm_x2(bh, ba);
                ldm_x2(bl, ba + 7680u);
                #pragma unroll
                for (int mb = 0; mb < 4; ++mb) {
                    mma_bf16(acc[mb][nb], ah[mb], bh);
                    mma_bf16(acc[mb][nb], ah[mb], bl);
                    mma_bf16(acc[mb][nb], al[mb], bh);
                }
            }
        }
    }

    const float alpha = *alpha_p;
    const int g = l >> 2, t2 = (l & 3) * 2;
    #pragma unroll
    for (int mb = 0; mb < 4; ++mb) {
        #pragma unroll
        for (int nb = 0; nb < 3; ++nb) {
            const int row = c0 + wm * 64 + mb * 16 + g;
            const int col = n0 + wn * 24 + nb * 8 + t2;
            const size_t o = ((size_t)b * CH + row) * NHW + col;
            float2 cv0 = *(const float2*)(cam + o);
            float2 cv1 = *(const float2*)(cam + o + 8 * NHW);
            *(float2*)(out + o) = make_float2(cv0.x + alpha * acc[mb][nb][0],
                                              cv0.y + alpha * acc[mb][nb][1]);
            *(float2*)(out + o + 8 * NHW) = make_float2(cv1.x + alpha * acc[mb][nb][2],
                                                        cv1.y + alpha * acc[mb][nb][3]);
        }
    }
}

// ---------------------------------------------------------------------------
extern "C" void kernel_launch(void* const* d_in, const int* in_sizes, int n_in,
                              void* d_out, int out_size) {
    const float* cam   = (const float*)d_in[0];
    const float* feat  = (const float*)d_in[1];
    const float* W1    = (const float*)d_in[2];
    const float* W2    = (const float*)d_in[3];
    const float* alpha = (const float*)d_in[4];
    float* out = (float*)d_out;

    cudaFuncSetAttribute(k_conv_mma,   cudaFuncAttributeMaxDynamicSharedMemorySize, 2 * KC_STAGE);
    cudaFuncSetAttribute(k_logits_mma, cudaFuncAttributeMaxDynamicSharedMemorySize, 2 * KL_STAGE);
    cudaFuncSetAttribute(k_out_mma,    cudaFuncAttributeMaxDynamicSharedMemorySize, 2 * KO_STAGE);

    k_cvt_cam<<<36864, 256>>>(cam);
    k_cvt_feat<<<36864, 256>>>(feat);
    k_cvt_w<<<1024, 256>>>(W1, W2);
    k_conv_mma<<<dim3(9, 2, 32), 256, 2 * KC_STAGE>>>();
    k_logits_mma<<<dim3(6, 6, 32), 256, 2 * KL_STAGE>>>();
    k_softmax<<<BATCH * NHW / 8, 256>>>();
    k_out_mma<<<dim3(6, 16, 32), 256, 2 * KO_STAGE>>>(cam, alpha, out);
}

// round 10
// speedup vs baseline: 1.0116x; 1.0116x over previous
#include <cuda_runtime.h>
#include <cuda_bf16.h>
#include <cstdint>

#define BATCH 32
#define CH    2048
#define NHW   576
#define MID   256

typedef unsigned long long u64;
typedef uint32_t u32;

// ------------------------- scratch (device globals) -------------------------
__device__ float g_attn[(size_t)BATCH * NHW * NHW];
__device__ __nv_bfloat16 g_cam_h[(size_t)BATCH * CH * NHW];
__device__ __nv_bfloat16 g_cam_l[(size_t)BATCH * CH * NHW];
__device__ __nv_bfloat16 g_feat_h[(size_t)BATCH * CH * NHW];
__device__ __nv_bfloat16 g_feat_l[(size_t)BATCH * CH * NHW];
__device__ __nv_bfloat16 g_attn_h[(size_t)BATCH * NHW * NHW];
__device__ __nv_bfloat16 g_attn_l[(size_t)BATCH * NHW * NHW];
__device__ __nv_bfloat16 g_Wh[512 * 2048];   // rows 0-255: W1, 256-511: W2
__device__ __nv_bfloat16 g_Wl[512 * 2048];
__device__ __nv_bfloat16 g_f1t_h[(size_t)BATCH * NHW * MID];
__device__ __nv_bfloat16 g_f1t_l[(size_t)BATCH * NHW * MID];
__device__ __nv_bfloat16 g_f2t_h[(size_t)BATCH * NHW * MID];
__device__ __nv_bfloat16 g_f2t_l[(size_t)BATCH * NHW * MID];

// ------------------------- helpers -------------------------
__device__ __forceinline__ u32 smem_u32(const void* p) {
    u32 a;
    asm("{ .reg .u64 t; cvta.to.shared.u64 t, %1; cvt.u32.u64 %0, t; }" : "=r"(a) : "l"(p));
    return a;
}
__device__ __forceinline__ u64 gaddr(const void* p) {
    u64 a; asm("cvta.to.global.u64 %0, %1;" : "=l"(a) : "l"(p)); return a;
}
__device__ __forceinline__ void cp16(u32 s, u64 g) {
    asm volatile("cp.async.cg.shared.global [%0], [%1], 16;" :: "r"(s), "l"(g) : "memory");
}
#define CP_COMMIT() asm volatile("cp.async.commit_group;" ::: "memory")
#define CP_WAIT(n)  asm volatile("cp.async.wait_group %0;" :: "n"(n) : "memory")

__device__ __forceinline__ void ldm_x4(u32* r, u32 a) {
    asm volatile("ldmatrix.sync.aligned.m8n8.x4.shared.b16 {%0,%1,%2,%3}, [%4];"
        : "=r"(r[0]), "=r"(r[1]), "=r"(r[2]), "=r"(r[3]) : "r"(a));
}
__device__ __forceinline__ void ldm_x2(u32* r, u32 a) {
    asm volatile("ldmatrix.sync.aligned.m8n8.x2.shared.b16 {%0,%1}, [%2];"
        : "=r"(r[0]), "=r"(r[1]) : "r"(a));
}
__device__ __forceinline__ void ldm_x2t(u32* r, u32 a) {
    asm volatile("ldmatrix.sync.aligned.m8n8.x2.trans.shared.b16 {%0,%1}, [%2];"
        : "=r"(r[0]), "=r"(r[1]) : "r"(a));
}
__device__ __forceinline__ void mma_bf16(float* d, const u32* a, const u32* b) {
    asm volatile(
        "mma.sync.aligned.m16n8k16.row.col.f32.bf16.bf16.f32 "
        "{%0,%1,%2,%3}, {%4,%5,%6,%7}, {%8,%9}, {%0,%1,%2,%3};"
        : "+f"(d[0]), "+f"(d[1]), "+f"(d[2]), "+f"(d[3])
        : "r"(a[0]), "r"(a[1]), "r"(a[2]), "r"(a[3]), "r"(b[0]), "r"(b[1]));
}

extern __shared__ __align__(16) char dsm[];

// ---------------------------------------------------------------------------
// Converters: fp32 -> (hi, lo) bf16 pair.
// ---------------------------------------------------------------------------
__device__ __forceinline__ void split4(float4 v, __nv_bfloat16* h, __nv_bfloat16* l, size_t i) {
    __nv_bfloat16 h0 = __float2bfloat16_rn(v.x), h1 = __float2bfloat16_rn(v.y);
    __nv_bfloat16 h2 = __float2bfloat16_rn(v.z), h3 = __float2bfloat16_rn(v.w);
    __nv_bfloat16 l0 = __float2bfloat16_rn(v.x - __bfloat162float(h0));
    __nv_bfloat16 l1 = __float2bfloat16_rn(v.y - __bfloat162float(h1));
    __nv_bfloat16 l2 = __float2bfloat16_rn(v.z - __bfloat162float(h2));
    __nv_bfloat16 l3 = __float2bfloat16_rn(v.w - __bfloat162float(h3));
    *(__nv_bfloat162*)(h + i)     = __nv_bfloat162(h0, h1);
    *(__nv_bfloat162*)(h + i + 2) = __nv_bfloat162(h2, h3);
    *(__nv_bfloat162*)(l + i)     = __nv_bfloat162(l0, l1);
    *(__nv_bfloat162*)(l + i + 2) = __nv_bfloat162(l2, l3);
}

__global__ __launch_bounds__(256) void k_cvt_cam(const float* __restrict__ src) {
    size_t i = ((size_t)blockIdx.x * 256 + threadIdx.x) * 4;
    split4(*(const float4*)(src + i), g_cam_h, g_cam_l, i);
}
__global__ __launch_bounds__(256) void k_cvt_feat(const float* __restrict__ src) {
    size_t i = ((size_t)blockIdx.x * 256 + threadIdx.x) * 4;
    split4(*(const float4*)(src + i), g_feat_h, g_feat_l, i);
}
__global__ __launch_bounds__(256) void k_cvt_w(const float* __restrict__ W1,
                                               const float* __restrict__ W2) {
    size_t i = ((size_t)blockIdx.x * 256 + threadIdx.x) * 4;
    const float* src = (i < (size_t)256 * 2048) ? (W1 + i) : (W2 + i - (size_t)256 * 2048);
    split4(*(const float4*)src, g_Wh, g_Wl, i);
}

// ---------------------------------------------------------------------------
// k_conv_mma (R8 config): [f1; f2] = [W1;W2](512x2048) @ feat(2048x576).
// BM=128, BN=144, K-chunk 32, 2-stage, one barrier per iter. 3-term split.
// ---------------------------------------------------------------------------
#define KC_STAGE 39936

__global__ __launch_bounds__(256) void k_conv_mma() {
    const int tid = threadIdx.x, wid = tid >> 5, l = tid & 31;
    const int b = blockIdx.z, m0 = blockIdx.y * 128, n0 = blockIdx.x * 144;
    const int wm = wid & 3, wn = wid >> 2;
    const u32 smb = smem_u32(dsm);

    const u64 gWh = gaddr(g_Wh), gWl = gaddr(g_Wl);
    const u64 gFh = gaddr(g_feat_h), gFl = gaddr(g_feat_l);

    float acc[2][9][4] = {};

    auto load_tiles = [&](int k0, u32 st) {
        #pragma unroll
        for (int t = 0; t < 9; ++t) {
            const int idx = tid + 256 * t;
            if (idx < 2176) {
                if (idx < 1024) {
                    const int a = idx & 511, r = a >> 2, c = a & 3;
                    const u64 g = ((idx < 512) ? gWh : gWl) +
                        ((u64)(m0 + r) * 2048 + (u32)(k0 + c * 8)) * 2;
                    cp16(st + ((idx < 512) ? 0u : 10240u) + (u32)r * 80 + (u32)c * 16, g);
                } else {
                    const int a2 = idx - 1024;
                    const int half = a2 >= 576;
                    const int j = a2 - (half ? 576 : 0);
                    const int r = j / 18, c = j - r * 18;
                    const u64 g = (half ? gFl : gFh) +
                        ((u64)(b * CH + k0 + r) * NHW + (u32)(n0 + c * 8)) * 2;
                    cp16(st + 20480u + (half ? 9728u : 0u) + (u32)r * 304 + (u32)c * 16, g);
                }
            }
        }
    };

    load_tiles(0, smb);
    CP_COMMIT();

    const u32 a_base = (u32)(wm * 32 + (l & 7) + ((l >> 3) & 1) * 8) * 80 + ((l >> 4) & 1) * 16;
    const int lb = l & 15;
    const u32 b_base = (u32)(((lb >> 3) & 1) * 8 + (lb & 7)) * 304 + (u32)(wn * 72) * 2;

    for (int it = 0; it < 64; ++it) {
        CP_WAIT(0);
        __syncthreads();
        if (it + 1 < 64) {
            load_tiles((it + 1) * 32, smb + (u32)((it + 1) & 1) * KC_STAGE);
            CP_COMMIT();
        }
        const u32 st = smb + (u32)(it & 1) * KC_STAGE;

        #pragma unroll
        for (int k16 = 0; k16 < 2; ++k16) {
            u32 ah[2][4], al[2][4];
            #pragma unroll
            for (int mb = 0; mb < 2; ++mb) {
                ldm_x4(ah[mb], st + a_base + (u32)mb * 1280 + (u32)k16 * 32);
                ldm_x4(al[mb], st + 10240u + a_base + (u32)mb * 1280 + (u32)k16 * 32);
            }
            #pragma unroll
            for (int nb = 0; nb < 9; ++nb) {
                u32 bh[2], bl[2];
                const u32 ba = st + 20480u + b_base + (u32)k16 * (16 * 304) + (u32)nb * 16;
                ldm_x2t(bh, ba);
                ldm_x2t(bl, ba + 9728u);
                #pragma unroll
                for (int mb = 0; mb < 2; ++mb) {
                    mma_bf16(acc[mb][nb], ah[mb], bh);
                    mma_bf16(acc[mb][nb], ah[mb], bl);
                    mma_bf16(acc[mb][nb], al[mb], bh);
                }
            }
        }
    }
    __syncthreads();

    // --- epilogue: smem transpose -> split bf16, write f{1,2}t[n][m] ---
    const int g = l >> 2, t2 = (l & 3) * 2;
    #pragma unroll
    for (int mb = 0; mb < 2; ++mb) {
        #pragma unroll
        for (int nb = 0; nb < 9; ++nb) {
            const int ml = wm * 32 + mb * 16 + g;
            const int nl = wn * 72 + nb * 8 + t2;
            #pragma unroll
            for (int q = 0; q < 4; ++q) {
                const float v = acc[mb][nb][q];
                const int m_ = ml + (q >> 1) * 8;
                const int n_ = nl + (q & 1);
                __nv_bfloat16 h = __float2bfloat16_rn(v);
                __nv_bfloat16 lo = __float2bfloat16_rn(v - __bfloat162float(h));
                *(__nv_bfloat16*)(dsm + (u32)n_ * 256 + (u32)m_ * 2) = h;
                *(__nv_bfloat16*)(dsm + 36864u + (u32)n_ * 256 + (u32)m_ * 2) = lo;
            }
        }
    }
    __syncthreads();

    __nv_bfloat16* dh = (m0 < 256) ? g_f1t_h : g_f2t_h;
    __nv_bfloat16* dl = (m0 < 256) ? g_f1t_l : g_f2t_l;
    const int cb0 = m0 & 255;
    #pragma unroll
    for (int t = 0; t < 9; ++t) {
        const int idx = tid + 256 * t;   // 0..2303
        const int j = idx >> 4, c = idx & 15;
        const size_t off = ((size_t)b * NHW + n0 + j) * MID + cb0 + c * 8;
        *(uint4*)(dh + off) = *(const uint4*)(dsm + (u32)j * 256 + (u32)c * 16);
        *(uint4*)(dl + off) = *(const uint4*)(dsm + 36864u + (u32)j * 256 + (u32)c * 16);
    }
}

// ---------------------------------------------------------------------------
// k_logits_mma: logits[i][j] = sum_m f1t[i][m]*f2t[j][m]. K=256, 3-term split.
// BM=BN=96, K-chunk 32, 2-stage, one barrier per iter.
// ---------------------------------------------------------------------------
#define KL_STAGE 30720

__global__ __launch_bounds__(256) void k_logits_mma() {
    const int tid = threadIdx.x, wid = tid >> 5, l = tid & 31;
    const int b = blockIdx.z, i0 = blockIdx.y * 96, j0 = blockIdx.x * 96;
    const int wm = wid & 1, wn = wid >> 1;
    const u32 smb = smem_u32(dsm);

    const u64 g1h = gaddr(g_f1t_h), g1l = gaddr(g_f1t_l);
    const u64 g2h = gaddr(g_f2t_h), g2l = gaddr(g_f2t_l);

    float acc[3][3][4] = {};

    auto load_tiles = [&](int k0, u32 st) {
        #pragma unroll
        for (int t = 0; t < 6; ++t) {
            const int idx = tid + 256 * t;
            const int side = idx >= 768;
            const int i2 = idx - (side ? 768 : 0);
            const int half = i2 >= 384;
            const int j2 = i2 - (half ? 384 : 0);
            const int r = j2 >> 2, c = j2 & 3;
            const u64 src = (side ? (half ? g2l : g2h) : (half ? g1l : g1h)) +
                ((u64)(b * NHW + (side ? j0 : i0) + r) * MID + (u32)(k0 + c * 8)) * 2;
            cp16(st + (side ? 15360u : 0u) + (half ? 7680u : 0u) + (u32)r * 80 + (u32)c * 16, src);
        }
    };

    load_tiles(0, smb);
    CP_COMMIT();

    const u32 a_base = (u32)(wm * 48 + (l & 7) + ((l >> 3) & 1) * 8) * 80 + ((l >> 4) & 1) * 16;
    const int lb = l & 15;
    const u32 b_base = (u32)(wn * 24 + (lb & 7)) * 80 + (u32)((lb >> 3) & 1) * 16;

    for (int it = 0; it < 8; ++it) {
        CP_WAIT(0);
        __syncthreads();
        if (it + 1 < 8) {
            load_tiles((it + 1) * 32, smb + (u32)((it + 1) & 1) * KL_STAGE);
            CP_COMMIT();
        }
        const u32 st = smb + (u32)(it & 1) * KL_STAGE;

        #pragma unroll
        for (int k16 = 0; k16 < 2; ++k16) {
            u32 ah[3][4], al[3][4];
            #pragma unroll
            for (int mb = 0; mb < 3; ++mb) {
                ldm_x4(ah[mb], st + a_base + (u32)mb * 1280 + (u32)k16 * 32);
                ldm_x4(al[mb], st + 7680u + a_base + (u32)mb * 1280 + (u32)k16 * 32);
            }
            #pragma unroll
            for (int nb = 0; nb < 3; ++nb) {
                u32 bh[2], bl[2];
                const u32 ba = st + 15360u + b_base + (u32)nb * 640 + (u32)k16 * 32;
                ldm_x2(bh, ba);
                ldm_x2(bl, ba + 7680u);
                #pragma unroll
                for (int mb = 0; mb < 3; ++mb) {
                    mma_bf16(acc[mb][nb], ah[mb], bh);
                    mma_bf16(acc[mb][nb], ah[mb], bl);
                    mma_bf16(acc[mb][nb], al[mb], bh);
                }
            }
        }
    }

    float* ab = g_attn + (size_t)b * NHW * NHW;
    const int g = l >> 2, t2 = (l & 3) * 2;
    #pragma unroll
    for (int mb = 0; mb < 3; ++mb) {
        #pragma unroll
        for (int nb = 0; nb < 3; ++nb) {
            const int row = i0 + wm * 48 + mb * 16 + g;
            const int col = j0 + wn * 24 + nb * 8 + t2;
            const size_t o = (size_t)row * NHW + col;
            *(float2*)(ab + o)           = make_float2(acc[mb][nb][0], acc[mb][nb][1]);
            *(float2*)(ab + o + 8 * NHW) = make_float2(acc[mb][nb][2], acc[mb][nb][3]);
        }
    }
}

// ---------------------------------------------------------------------------
// k_softmax: warp-per-row (576 elems, 18/lane), 8 rows per 256-thread block.
// ---------------------------------------------------------------------------
__global__ __launch_bounds__(256) void k_softmax() {
    const int wid = threadIdx.x >> 5, l = threadIdx.x & 31;
    const size_t row = (size_t)blockIdx.x * 8 + wid;
    const float* p = g_attn + row * NHW;
    __nv_bfloat16* oh = g_attn_h + row * NHW;
    __nv_bfloat16* ol = g_attn_l + row * NHW;

    float v[18];
    float m = -1e30f;
    #pragma unroll
    for (int i = 0; i < 18; ++i) { v[i] = p[l + 32 * i]; m = fmaxf(m, v[i]); }
    #pragma unroll
    for (int o = 16; o > 0; o >>= 1) m = fmaxf(m, __shfl_xor_sync(0xffffffffu, m, o));

    float s = 0.f;
    #pragma unroll
    for (int i = 0; i < 18; ++i) { v[i] = __expf(v[i] - m); s += v[i]; }
    #pragma unroll
    for (int o = 16; o > 0; o >>= 1) s += __shfl_xor_sync(0xffffffffu, s, o);

    const float inv = 1.0f / s;
    #pragma unroll
    for (int i = 0; i < 18; ++i) {
        float pv = v[i] * inv;
        __nv_bfloat16 h = __float2bfloat16_rn(pv);
        __nv_bfloat16 lo = __float2bfloat16_rn(pv - __bfloat162float(h));
        oh[l + 32 * i] = h;
        ol[l + 32 * i] = lo;
    }
}

// ---------------------------------------------------------------------------
// k_out_mma: out[c][n] = cam[c][n] + alpha * sum_k cam[c][k]*attn[n][k]
// NEW: BM=128, BN=144, warps 4x2 (32 rows x 72 cols). K-chunk 32, 2-stage.
// stage: Ah(10240) Al(10240) Bh 144x80 (11520) Bl (11520) = 43520. 2 CTAs/SM.
// ---------------------------------------------------------------------------
#define KO_STAGE 43520

__global__ __launch_bounds__(256) void k_out_mma(const float* __restrict__ cam,
                                                 const float* __restrict__ alpha_p,
                                                 float* __restrict__ out) {
    const int tid = threadIdx.x, wid = tid >> 5, l = tid & 31;
    const int b = blockIdx.z, c0 = blockIdx.y * 128, n0 = blockIdx.x * 144;
    const int wm = wid & 3, wn = wid >> 2;
    const u32 smb = smem_u32(dsm);

    const u64 gCh = gaddr(g_cam_h), gCl = gaddr(g_cam_l);
    const u64 gAh = gaddr(g_attn_h), gAl = gaddr(g_attn_l);

    float acc[2][9][4] = {};

    auto load_tiles = [&](int k0, u32 st) {
        #pragma unroll
        for (int t = 0; t < 9; ++t) {
            const int idx = tid + 256 * t;   // 0..2303, used 0..2175
            if (idx < 2176) {
                if (idx < 1024) {
                    const int a = idx & 511, r = a >> 2, c = a & 3;
                    const u64 g = ((idx < 512) ? gCh : gCl) +
                        ((u64)(b * CH + c0 + r) * NHW + (u32)(k0 + c * 8)) * 2;
                    cp16(st + ((idx < 512) ? 0u : 10240u) + (u32)r * 80 + (u32)c * 16, g);
                } else {
                    const int j = idx - 1024;        // 0..1151
                    const int half = j >= 576;
                    const int j2 = j - (half ? 576 : 0);
                    const int r = j2 >> 2, c = j2 & 3;
                    const u64 g = (half ? gAl : gAh) +
                        ((u64)(b * NHW + n0 + r) * NHW + (u32)(k0 + c * 8)) * 2;
                    cp16(st + 20480u + (half ? 11520u : 0u) + (u32)r * 80 + (u32)c * 16, g);
                }
            }
        }
    };

    load_tiles(0, smb);
    CP_COMMIT();

    const u32 a_base = (u32)(wm * 32 + (l & 7) + ((l >> 3) & 1) * 8) * 80 + ((l >> 4) & 1) * 16;
    const int lb = l & 15;
    const u32 b_base = (u32)(wn * 72 + (lb & 7)) * 80 + (u32)((lb >> 3) & 1) * 16;

    for (int it = 0; it < 18; ++it) {
        CP_WAIT(0);
        __syncthreads();
        if (it + 1 < 18) {
            load_tiles((it + 1) * 32, smb + (u32)((it + 1) & 1) * KO_STAGE);
            CP_COMMIT();
        }
        const u32 st = smb + (u32)(it & 1) * KO_STAGE;

        #pragma unroll
        for (int k16 = 0; k16 < 2; ++k16) {
            u32 ah[2][4], al[2][4];
            #pragma unroll
            for (int mb = 0; mb < 2; ++mb) {
                ldm_x4(ah[mb], st + a_base + (u32)mb * 1280 + (u32)k16 * 32);
                ldm_x4(al[mb], st + 10240u + a_base + (u32)mb * 1280 + (u32)k16 * 32);
            }
            #pragma unroll
            for (int nb = 0; nb < 9; ++nb) {
                u32 bh[2], bl[2];
                const u32 ba = st + 20480u + b_base + (u32)nb * 640 + (u32)k16 * 32;
                ldm_x2(bh, ba);
                ldm_x2(bl, ba + 11520u);
                #pragma unroll
                for (int mb = 0; mb < 2; ++mb) {
                    mma_bf16(acc[mb][nb], ah[mb], bh);
                    mma_bf16(acc[mb][nb], ah[mb], bl);
                    mma_bf16(acc[mb][nb], al[mb], bh);
                }
            }
        }
    }

    const float alpha = *alpha_p;
    const int g = l >> 2, t2 = (l & 3) * 2;
    #pragma unroll
    for (int mb = 0; mb < 2; ++mb) {
        #pragma unroll
        for (int nb = 0; nb < 9; ++nb) {
            const int row = c0 + wm * 32 + mb * 16 + g;
            const int col = n0 + wn * 72 + nb * 8 + t2;
            const size_t o = ((size_t)b * CH + row) * NHW + col;
            float2 cv0 = *(const float2*)(cam + o);
            float2 cv1 = *(const float2*)(cam + o + 8 * NHW);
            *(float2*)(out + o) = make_float2(cv0.x + alpha * acc[mb][nb][0],
                                              cv0.y + alpha * acc[mb][nb][1]);
            *(float2*)(out + o + 8 * NHW) = make_float2(cv1.x + alpha * acc[mb][nb][2],
                                                        cv1.y + alpha * acc[mb][nb][3]);
        }
    }
}

// ---------------------------------------------------------------------------
extern "C" void kernel_launch(void* const* d_in, const int* in_sizes, int n_in,
                              void* d_out, int out_size) {
    const float* cam   = (const float*)d_in[0];
    const float* feat  = (const float*)d_in[1];
    const float* W1    = (const float*)d_in[2];
    const float* W2    = (const float*)d_in[3];
    const float* alpha = (const float*)d_in[4];
    float* out = (float*)d_out;

    cudaFuncSetAttribute(k_conv_mma,   cudaFuncAttributeMaxDynamicSharedMemorySize, 2 * KC_STAGE);
    cudaFuncSetAttribute(k_logits_mma, cudaFuncAttributeMaxDynamicSharedMemorySize, 2 * KL_STAGE);
    cudaFuncSetAttribute(k_out_mma,    cudaFuncAttributeMaxDynamicSharedMemorySize, 2 * KO_STAGE);

    k_cvt_cam<<<36864, 256>>>(cam);
    k_cvt_feat<<<36864, 256>>>(feat);
    k_cvt_w<<<1024, 256>>>(W1, W2);
    k_conv_mma<<<dim3(4, 4, 32), 256, 2 * KC_STAGE>>>();
    k_logits_mma<<<dim3(6, 6, 32), 256, 2 * KL_STAGE>>>();
    k_softmax<<<BATCH * NHW / 8, 256>>>();
    k_out_mma<<<dim3(4, 16, 32), 256, 2 * KO_STAGE>>>(cam, alpha, out);
}

// round 12
// speedup vs baseline: 1.2218x; 1.2078x over previous
#include <cuda_runtime.h>
#include <cuda_bf16.h>
#include <cuda_fp16.h>
#include <cstdint>

#define BATCH 32
#define CH    2048
#define NHW   576
#define MID   256

typedef unsigned long long u64;
typedef uint32_t u32;

// ------------------------- scratch (device globals) -------------------------
__device__ float g_attn[(size_t)BATCH * NHW * NHW];
__device__ __half g_cam_h[(size_t)BATCH * CH * NHW];   // fp16 hi limb of cam
__device__ __half g_cam_l[(size_t)BATCH * CH * NHW];   // fp16 lo limb of cam
__device__ __nv_bfloat16 g_feat_h[(size_t)BATCH * CH * NHW];
__device__ __nv_bfloat16 g_feat_l[(size_t)BATCH * CH * NHW];
__device__ __half g_attn_fp16[(size_t)BATCH * NHW * NHW];  // single fp16 attn
__device__ __nv_bfloat16 g_Wh[512 * 2048];   // rows 0-255: W1, 256-511: W2
__device__ __nv_bfloat16 g_Wl[512 * 2048];
__device__ __nv_bfloat16 g_f1t_h[(size_t)BATCH * NHW * MID];
__device__ __nv_bfloat16 g_f1t_l[(size_t)BATCH * NHW * MID];
__device__ __nv_bfloat16 g_f2t_h[(size_t)BATCH * NHW * MID];
__device__ __nv_bfloat16 g_f2t_l[(size_t)BATCH * NHW * MID];

// ------------------------- helpers -------------------------
__device__ __forceinline__ u32 smem_u32(const void* p) {
    u32 a;
    asm("{ .reg .u64 t; cvta.to.shared.u64 t, %1; cvt.u32.u64 %0, t; }" : "=r"(a) : "l"(p));
    return a;
}
__device__ __forceinline__ u64 gaddr(const void* p) {
    u64 a; asm("cvta.to.global.u64 %0, %1;" : "=l"(a) : "l"(p)); return a;
}
__device__ __forceinline__ void cp16(u32 s, u64 g) {
    asm volatile("cp.async.cg.shared.global [%0], [%1], 16;" :: "r"(s), "l"(g) : "memory");
}
#define CP_COMMIT() asm volatile("cp.async.commit_group;" ::: "memory")
#define CP_WAIT(n)  asm volatile("cp.async.wait_group %0;" :: "n"(n) : "memory")

__device__ __forceinline__ void ldm_x4(u32* r, u32 a) {
    asm volatile("ldmatrix.sync.aligned.m8n8.x4.shared.b16 {%0,%1,%2,%3}, [%4];"
        : "=r"(r[0]), "=r"(r[1]), "=r"(r[2]), "=r"(r[3]) : "r"(a));
}
__device__ __forceinline__ void ldm_x2(u32* r, u32 a) {
    asm volatile("ldmatrix.sync.aligned.m8n8.x2.shared.b16 {%0,%1}, [%2];"
        : "=r"(r[0]), "=r"(r[1]) : "r"(a));
}
__device__ __forceinline__ void ldm_x2t(u32* r, u32 a) {
    asm volatile("ldmatrix.sync.aligned.m8n8.x2.trans.shared.b16 {%0,%1}, [%2];"
        : "=r"(r[0]), "=r"(r[1]) : "r"(a));
}
__device__ __forceinline__ void mma_bf16(float* d, const u32* a, const u32* b) {
    asm volatile(
        "mma.sync.aligned.m16n8k16.row.col.f32.bf16.bf16.f32 "
        "{%0,%1,%2,%3}, {%4,%5,%6,%7}, {%8,%9}, {%0,%1,%2,%3};"
        : "+f"(d[0]), "+f"(d[1]), "+f"(d[2]), "+f"(d[3])
        : "r"(a[0]), "r"(a[1]), "r"(a[2]), "r"(a[3]), "r"(b[0]), "r"(b[1]));
}
__device__ __forceinline__ void mma_f16(float* d, const u32* a, const u32* b) {
    asm volatile(
        "mma.sync.aligned.m16n8k16.row.col.f32.f16.f16.f32 "
        "{%0,%1,%2,%3}, {%4,%5,%6,%7}, {%8,%9}, {%0,%1,%2,%3};"
        : "+f"(d[0]), "+f"(d[1]), "+f"(d[2]), "+f"(d[3])
        : "r"(a[0]), "r"(a[1]), "r"(a[2]), "r"(a[3]), "r"(b[0]), "r"(b[1]));
}

extern __shared__ __align__(16) char dsm[];

// ---------------------------------------------------------------------------
// Converters.
// ---------------------------------------------------------------------------
__device__ __forceinline__ void split4(float4 v, __nv_bfloat16* h, __nv_bfloat16* l, size_t i) {
    __nv_bfloat16 h0 = __float2bfloat16_rn(v.x), h1 = __float2bfloat16_rn(v.y);
    __nv_bfloat16 h2 = __float2bfloat16_rn(v.z), h3 = __float2bfloat16_rn(v.w);
    __nv_bfloat16 l0 = __float2bfloat16_rn(v.x - __bfloat162float(h0));
    __nv_bfloat16 l1 = __float2bfloat16_rn(v.y - __bfloat162float(h1));
    __nv_bfloat16 l2 = __float2bfloat16_rn(v.z - __bfloat162float(h2));
    __nv_bfloat16 l3 = __float2bfloat16_rn(v.w - __bfloat162float(h3));
    *(__nv_bfloat162*)(h + i)     = __nv_bfloat162(h0, h1);
    *(__nv_bfloat162*)(h + i + 2) = __nv_bfloat162(h2, h3);
    *(__nv_bfloat162*)(l + i)     = __nv_bfloat162(l0, l1);
    *(__nv_bfloat162*)(l + i + 2) = __nv_bfloat162(l2, l3);
}

// cam -> fp16 (hi, lo) limbs
__global__ __launch_bounds__(256) void k_cvt_cam(const float* __restrict__ src) {
    size_t i = ((size_t)blockIdx.x * 256 + threadIdx.x) * 4;
    float4 v = *(const float4*)(src + i);
    __half h0 = __float2half_rn(v.x), h1 = __float2half_rn(v.y);
    __half h2 = __float2half_rn(v.z), h3 = __float2half_rn(v.w);
    __half l0 = __float2half_rn(v.x - __half2float(h0));
    __half l1 = __float2half_rn(v.y - __half2float(h1));
    __half l2 = __float2half_rn(v.z - __half2float(h2));
    __half l3 = __float2half_rn(v.w - __half2float(h3));
    *(__half2*)(g_cam_h + i)     = __half2(h0, h1);
    *(__half2*)(g_cam_h + i + 2) = __half2(h2, h3);
    *(__half2*)(g_cam_l + i)     = __half2(l0, l1);
    *(__half2*)(g_cam_l + i + 2) = __half2(l2, l3);
}
__global__ __launch_bounds__(256) void k_cvt_feat(const float* __restrict__ src) {
    size_t i = ((size_t)blockIdx.x * 256 + threadIdx.x) * 4;
    split4(*(const float4*)(src + i), g_feat_h, g_feat_l, i);
}
__global__ __launch_bounds__(256) void k_cvt_w(const float* __restrict__ W1,
                                               const float* __restrict__ W2) {
    size_t i = ((size_t)blockIdx.x * 256 + threadIdx.x) * 4;
    const float* src = (i < (size_t)256 * 2048) ? (W1 + i) : (W2 + i - (size_t)256 * 2048);
    split4(*(const float4*)src, g_Wh, g_Wl, i);
}

// ---------------------------------------------------------------------------
// k_conv_mma (R8 config, unchanged): [f1; f2] = [W1;W2] @ feat. bf16 3-term.
// BM=128, BN=144, K-chunk 32, 2-stage, one barrier per iter.
// ---------------------------------------------------------------------------
#define KC_STAGE 39936

__global__ __launch_bounds__(256) void k_conv_mma() {
    const int tid = threadIdx.x, wid = tid >> 5, l = tid & 31;
    const int b = blockIdx.z, m0 = blockIdx.y * 128, n0 = blockIdx.x * 144;
    const int wm = wid & 3, wn = wid >> 2;
    const u32 smb = smem_u32(dsm);

    const u64 gWh = gaddr(g_Wh), gWl = gaddr(g_Wl);
    const u64 gFh = gaddr(g_feat_h), gFl = gaddr(g_feat_l);

    float acc[2][9][4] = {};

    auto load_tiles = [&](int k0, u32 st) {
        #pragma unroll
        for (int t = 0; t < 9; ++t) {
            const int idx = tid + 256 * t;
            if (idx < 2176) {
                if (idx < 1024) {
                    const int a = idx & 511, r = a >> 2, c = a & 3;
                    const u64 g = ((idx < 512) ? gWh : gWl) +
                        ((u64)(m0 + r) * 2048 + (u32)(k0 + c * 8)) * 2;
                    cp16(st + ((idx < 512) ? 0u : 10240u) + (u32)r * 80 + (u32)c * 16, g);
                } else {
                    const int a2 = idx - 1024;
                    const int half = a2 >= 576;
                    const int j = a2 - (half ? 576 : 0);
                    const int r = j / 18, c = j - r * 18;
                    const u64 g = (half ? gFl : gFh) +
                        ((u64)(b * CH + k0 + r) * NHW + (u32)(n0 + c * 8)) * 2;
                    cp16(st + 20480u + (half ? 9728u : 0u) + (u32)r * 304 + (u32)c * 16, g);
                }
            }
        }
    };

    load_tiles(0, smb);
    CP_COMMIT();

    const u32 a_base = (u32)(wm * 32 + (l & 7) + ((l >> 3) & 1) * 8) * 80 + ((l >> 4) & 1) * 16;
    const int lb = l & 15;
    const u32 b_base = (u32)(((lb >> 3) & 1) * 8 + (lb & 7)) * 304 + (u32)(wn * 72) * 2;

    for (int it = 0; it < 64; ++it) {
        CP_WAIT(0);
        __syncthreads();
        if (it + 1 < 64) {
            load_tiles((it + 1) * 32, smb + (u32)((it + 1) & 1) * KC_STAGE);
            CP_COMMIT();
        }
        const u32 st = smb + (u32)(it & 1) * KC_STAGE;

        #pragma unroll
        for (int k16 = 0; k16 < 2; ++k16) {
            u32 ah[2][4], al[2][4];
            #pragma unroll
            for (int mb = 0; mb < 2; ++mb) {
                ldm_x4(ah[mb], st + a_base + (u32)mb * 1280 + (u32)k16 * 32);
                ldm_x4(al[mb], st + 10240u + a_base + (u32)mb * 1280 + (u32)k16 * 32);
            }
            #pragma unroll
            for (int nb = 0; nb < 9; ++nb) {
                u32 bh[2], bl[2];
                const u32 ba = st + 20480u + b_base + (u32)k16 * (16 * 304) + (u32)nb * 16;
                ldm_x2t(bh, ba);
                ldm_x2t(bl, ba + 9728u);
                #pragma unroll
                for (int mb = 0; mb < 2; ++mb) {
                    mma_bf16(acc[mb][nb], ah[mb], bh);
                    mma_bf16(acc[mb][nb], ah[mb], bl);
                    mma_bf16(acc[mb][nb], al[mb], bh);
                }
            }
        }
    }
    __syncthreads();

    // --- epilogue: smem transpose -> split bf16, write f{1,2}t[n][m] ---
    const int g = l >> 2, t2 = (l & 3) * 2;
    #pragma unroll
    for (int mb = 0; mb < 2; ++mb) {
        #pragma unroll
        for (int nb = 0; nb < 9; ++nb) {
            const int ml = wm * 32 + mb * 16 + g;
            const int nl = wn * 72 + nb * 8 + t2;
            #pragma unroll
            for (int q = 0; q < 4; ++q) {
                const float v = acc[mb][nb][q];
                const int m_ = ml + (q >> 1) * 8;
                const int n_ = nl + (q & 1);
                __nv_bfloat16 h = __float2bfloat16_rn(v);
                __nv_bfloat16 lo = __float2bfloat16_rn(v - __bfloat162float(h));
                *(__nv_bfloat16*)(dsm + (u32)n_ * 256 + (u32)m_ * 2) = h;
                *(__nv_bfloat16*)(dsm + 36864u + (u32)n_ * 256 + (u32)m_ * 2) = lo;
            }
        }
    }
    __syncthreads();

    __nv_bfloat16* dh = (m0 < 256) ? g_f1t_h : g_f2t_h;
    __nv_bfloat16* dl = (m0 < 256) ? g_f1t_l : g_f2t_l;
    const int cb0 = m0 & 255;
    #pragma unroll
    for (int t = 0; t < 9; ++t) {
        const int idx = tid + 256 * t;
        const int j = idx >> 4, c = idx & 15;
        const size_t off = ((size_t)b * NHW + n0 + j) * MID + cb0 + c * 8;
        *(uint4*)(dh + off) = *(const uint4*)(dsm + (u32)j * 256 + (u32)c * 16);
        *(uint4*)(dl + off) = *(const uint4*)(dsm + 36864u + (u32)j * 256 + (u32)c * 16);
    }
}

// ---------------------------------------------------------------------------
// k_logits_mma (unchanged): logits = f1t f2t^T. K=256, bf16 3-term.
// ---------------------------------------------------------------------------
#define KL_STAGE 30720

__global__ __launch_bounds__(256) void k_logits_mma() {
    const int tid = threadIdx.x, wid = tid >> 5, l = tid & 31;
    const int b = blockIdx.z, i0 = blockIdx.y * 96, j0 = blockIdx.x * 96;
    const int wm = wid & 1, wn = wid >> 1;
    const u32 smb = smem_u32(dsm);

    const u64 g1h = gaddr(g_f1t_h), g1l = gaddr(g_f1t_l);
    const u64 g2h = gaddr(g_f2t_h), g2l = gaddr(g_f2t_l);

    float acc[3][3][4] = {};

    auto load_tiles = [&](int k0, u32 st) {
        #pragma unroll
        for (int t = 0; t < 6; ++t) {
            const int idx = tid + 256 * t;
            const int side = idx >= 768;
            const int i2 = idx - (side ? 768 : 0);
            const int half = i2 >= 384;
            const int j2 = i2 - (half ? 384 : 0);
            const int r = j2 >> 2, c = j2 & 3;
            const u64 src = (side ? (half ? g2l : g2h) : (half ? g1l : g1h)) +
                ((u64)(b * NHW + (side ? j0 : i0) + r) * MID + (u32)(k0 + c * 8)) * 2;
            cp16(st + (side ? 15360u : 0u) + (half ? 7680u : 0u) + (u32)r * 80 + (u32)c * 16, src);
        }
    };

    load_tiles(0, smb);
    CP_COMMIT();

    const u32 a_base = (u32)(wm * 48 + (l & 7) + ((l >> 3) & 1) * 8) * 80 + ((l >> 4) & 1) * 16;
    const int lb = l & 15;
    const u32 b_base = (u32)(wn * 24 + (lb & 7)) * 80 + (u32)((lb >> 3) & 1) * 16;

    for (int it = 0; it < 8; ++it) {
        CP_WAIT(0);
        __syncthreads();
        if (it + 1 < 8) {
            load_tiles((it + 1) * 32, smb + (u32)((it + 1) & 1) * KL_STAGE);
            CP_COMMIT();
        }
        const u32 st = smb + (u32)(it & 1) * KL_STAGE;

        #pragma unroll
        for (int k16 = 0; k16 < 2; ++k16) {
            u32 ah[3][4], al[3][4];
            #pragma unroll
            for (int mb = 0; mb < 3; ++mb) {
                ldm_x4(ah[mb], st + a_base + (u32)mb * 1280 + (u32)k16 * 32);
                ldm_x4(al[mb], st + 7680u + a_base + (u32)mb * 1280 + (u32)k16 * 32);
            }
            #pragma unroll
            for (int nb = 0; nb < 3; ++nb) {
                u32 bh[2], bl[2];
                const u32 ba = st + 15360u + b_base + (u32)nb * 640 + (u32)k16 * 32;
                ldm_x2(bh, ba);
                ldm_x2(bl, ba + 7680u);
                #pragma unroll
                for (int mb = 0; mb < 3; ++mb) {
                    mma_bf16(acc[mb][nb], ah[mb], bh);
                    mma_bf16(acc[mb][nb], ah[mb], bl);
                    mma_bf16(acc[mb][nb], al[mb], bh);
                }
            }
        }
    }

    float* ab = g_attn + (size_t)b * NHW * NHW;
    const int g = l >> 2, t2 = (l & 3) * 2;
    #pragma unroll
    for (int mb = 0; mb < 3; ++mb) {
        #pragma unroll
        for (int nb = 0; nb < 3; ++nb) {
            const int row = i0 + wm * 48 + mb * 16 + g;
            const int col = j0 + wn * 24 + nb * 8 + t2;
            const size_t o = (size_t)row * NHW + col;
            *(float2*)(ab + o)           = make_float2(acc[mb][nb][0], acc[mb][nb][1]);
            *(float2*)(ab + o + 8 * NHW) = make_float2(acc[mb][nb][2], acc[mb][nb][3]);
        }
    }
}

// ---------------------------------------------------------------------------
// k_softmax: warp-per-row; emits single fp16 attn.
// ---------------------------------------------------------------------------
__global__ __launch_bounds__(256) void k_softmax() {
    const int wid = threadIdx.x >> 5, l = threadIdx.x & 31;
    const size_t row = (size_t)blockIdx.x * 8 + wid;
    const float* p = g_attn + row * NHW;
    __half* oh = g_attn_fp16 + row * NHW;

    float v[18];
    float m = -1e30f;
    #pragma unroll
    for (int i = 0; i < 18; ++i) { v[i] = p[l + 32 * i]; m = fmaxf(m, v[i]); }
    #pragma unroll
    for (int o = 16; o > 0; o >>= 1) m = fmaxf(m, __shfl_xor_sync(0xffffffffu, m, o));

    float s = 0.f;
    #pragma unroll
    for (int i = 0; i < 18; ++i) { v[i] = __expf(v[i] - m); s += v[i]; }
    #pragma unroll
    for (int o = 16; o > 0; o >>= 1) s += __shfl_xor_sync(0xffffffffu, s, o);

    const float inv = 1.0f / s;
    #pragma unroll
    for (int i = 0; i < 18; ++i) {
        oh[l + 32 * i] = __float2half_rn(v[i] * inv);
    }
}

// ---------------------------------------------------------------------------
// k_out_mma: out = cam + alpha * cam@attn^T.
// fp16 2-term: camh*attn + caml*attn (exact in cam; only attn fp16 rounding).
// BM=128, BN=144, warps 4wm x 2wn. K-chunk 32, 2-stage, one barrier/iter.
// stage: Ah(10240) Al(10240) B 144x80 (11520) = 32000. Forced 2 CTAs/SM.
// ---------------------------------------------------------------------------
#define KO_STAGE 32000

__global__ __launch_bounds__(256, 2) void k_out_mma(const float* __restrict__ cam,
                                                    const float* __restrict__ alpha_p,
                                                    float* __restrict__ out) {
    const int tid = threadIdx.x, wid = tid >> 5, l = tid & 31;
    const int b = blockIdx.z, c0 = blockIdx.y * 128, n0 = blockIdx.x * 144;
    const int wm = wid & 3, wn = wid >> 2;
    const u32 smb = smem_u32(dsm);

    const u64 gCh = gaddr(g_cam_h), gCl = gaddr(g_cam_l);
    const u64 gA  = gaddr(g_attn_fp16);

    float acc[2][9][4] = {};

    auto load_tiles = [&](int k0, u32 st) {
        #pragma unroll
        for (int t = 0; t < 7; ++t) {
            const int idx = tid + 256 * t;   // used 0..1599
            if (idx < 1600) {
                if (idx < 1024) {
                    const int layer = idx >= 512;
                    const int a = idx & 511, r = a >> 2, c = a & 3;
                    const u64 g = (layer ? gCl : gCh) +
                        ((u64)(b * CH + c0 + r) * NHW + (u32)(k0 + c * 8)) * 2;
                    cp16(st + (u32)layer * 10240u + (u32)r * 80 + (u32)c * 16, g);
                } else {
                    const int j = idx - 1024;       // 0..575
                    const int r = j >> 2, c = j & 3;
                    const u64 g = gA +
                        ((u64)(b * NHW + n0 + r) * NHW + (u32)(k0 + c * 8)) * 2;
                    cp16(st + 20480u + (u32)r * 80 + (u32)c * 16, g);
                }
            }
        }
    };

    load_tiles(0, smb);
    CP_COMMIT();

    const u32 a_base = (u32)(wm * 32 + (l & 7) + ((l >> 3) & 1) * 8) * 80 + ((l >> 4) & 1) * 16;
    const int lb = l & 15;
    const u32 b_base = (u32)(wn * 72 + (lb & 7)) * 80 + (u32)((lb >> 3) & 1) * 16;

    for (int it = 0; it < 18; ++it) {
        CP_WAIT(0);
        __syncthreads();
        if (it + 1 < 18) {
            load_tiles((it + 1) * 32, smb + (u32)((it + 1) & 1) * KO_STAGE);
            CP_COMMIT();
        }
        const u32 st = smb + (u32)(it & 1) * KO_STAGE;

        #pragma unroll
        for (int k16 = 0; k16 < 2; ++k16) {
            u32 ah[2][4], al[2][4];
            #pragma unroll
            for (int mb = 0; mb < 2; ++mb) {
                ldm_x4(ah[mb], st + a_base + (u32)mb * 1280 + (u32)k16 * 32);
                ldm_x4(al[mb], st + 10240u + a_base + (u32)mb * 1280 + (u32)k16 * 32);
            }
            #pragma unroll
            for (int nb = 0; nb < 9; ++nb) {
                u32 bh[2];
                ldm_x2(bh, st + 20480u + b_base + (u32)nb * 640 + (u32)k16 * 32);
                #pragma unroll
                for (int mb = 0; mb < 2; ++mb) {
                    mma_f16(acc[mb][nb], ah[mb], bh);
                    mma_f16(acc[mb][nb], al[mb], bh);
                }
            }
        }
    }

    const float alpha = *alpha_p;
    const int g = l >> 2, t2 = (l & 3) * 2;
    #pragma unroll
    for (int mb = 0; mb < 2; ++mb) {
        #pragma unroll
        for (int nb = 0; nb < 9; ++nb) {
            const int row = c0 + wm * 32 + mb * 16 + g;
            const int col = n0 + wn * 72 + nb * 8 + t2;
            const size_t o = ((size_t)b * CH + row) * NHW + col;
            float2 cv0 = *(const float2*)(cam + o);
            float2 cv1 = *(const float2*)(cam + o + 8 * NHW);
            *(float2*)(out + o) = make_float2(cv0.x + alpha * acc[mb][nb][0],
                                              cv0.y + alpha * acc[mb][nb][1]);
            *(float2*)(out + o + 8 * NHW) = make_float2(cv1.x + alpha * acc[mb][nb][2],
                                                        cv1.y + alpha * acc[mb][nb][3]);
        }
    }
}

// ---------------------------------------------------------------------------
extern "C" void kernel_launch(void* const* d_in, const int* in_sizes, int n_in,
                              void* d_out, int out_size) {
    const float* cam   = (const float*)d_in[0];
    const float* feat  = (const float*)d_in[1];
    const float* W1    = (const float*)d_in[2];
    const float* W2    = (const float*)d_in[3];
    const float* alpha = (const float*)d_in[4];
    float* out = (float*)d_out;

    cudaFuncSetAttribute(k_conv_mma,   cudaFuncAttributeMaxDynamicSharedMemorySize, 2 * KC_STAGE);
    cudaFuncSetAttribute(k_logits_mma, cudaFuncAttributeMaxDynamicSharedMemorySize, 2 * KL_STAGE);
    cudaFuncSetAttribute(k_out_mma,    cudaFuncAttributeMaxDynamicSharedMemorySize, 2 * KO_STAGE);

    k_cvt_cam<<<36864, 256>>>(cam);
    k_cvt_feat<<<36864, 256>>>(feat);
    k_cvt_w<<<1024, 256>>>(W1, W2);
    k_conv_mma<<<dim3(4, 4, 32), 256, 2 * KC_STAGE>>>();
    k_logits_mma<<<dim3(6, 6, 32), 256, 2 * KL_STAGE>>>();
    k_softmax<<<BATCH * NHW / 8, 256>>>();
    k_out_mma<<<dim3(4, 16, 32), 256, 2 * KO_STAGE>>>(cam, alpha, out);
}

// round 13
// speedup vs baseline: 1.4281x; 1.1688x over previous
#include <cuda_runtime.h>
#include <cuda_bf16.h>
#include <cuda_fp16.h>
#include <cstdint>

#define BATCH 32
#define CH    2048
#define NHW   576
#define MID   256

typedef unsigned long long u64;
typedef uint32_t u32;

// ------------------------- scratch (device globals) -------------------------
__device__ float g_attn[(size_t)BATCH * NHW * NHW];
__device__ __half g_cam_h[(size_t)BATCH * CH * NHW];   // fp16 cam (single limb)
__device__ __nv_bfloat16 g_feat_h[(size_t)BATCH * CH * NHW];
__device__ __nv_bfloat16 g_feat_l[(size_t)BATCH * CH * NHW];
__device__ __half g_attn_fp16[(size_t)BATCH * NHW * NHW];  // single fp16 attn
__device__ __nv_bfloat16 g_Wh[512 * 2048];   // rows 0-255: W1, 256-511: W2
__device__ __nv_bfloat16 g_Wl[512 * 2048];
__device__ __nv_bfloat16 g_f1t_h[(size_t)BATCH * NHW * MID];
__device__ __nv_bfloat16 g_f1t_l[(size_t)BATCH * NHW * MID];
__device__ __nv_bfloat16 g_f2t_h[(size_t)BATCH * NHW * MID];
__device__ __nv_bfloat16 g_f2t_l[(size_t)BATCH * NHW * MID];

// ------------------------- helpers -------------------------
__device__ __forceinline__ u32 smem_u32(const void* p) {
    u32 a;
    asm("{ .reg .u64 t; cvta.to.shared.u64 t, %1; cvt.u32.u64 %0, t; }" : "=r"(a) : "l"(p));
    return a;
}
__device__ __forceinline__ u64 gaddr(const void* p) {
    u64 a; asm("cvta.to.global.u64 %0, %1;" : "=l"(a) : "l"(p)); return a;
}
__device__ __forceinline__ void cp16(u32 s, u64 g) {
    asm volatile("cp.async.cg.shared.global [%0], [%1], 16;" :: "r"(s), "l"(g) : "memory");
}
#define CP_COMMIT() asm volatile("cp.async.commit_group;" ::: "memory")
#define CP_WAIT(n)  asm volatile("cp.async.wait_group %0;" :: "n"(n) : "memory")

__device__ __forceinline__ void ldm_x4(u32* r, u32 a) {
    asm volatile("ldmatrix.sync.aligned.m8n8.x4.shared.b16 {%0,%1,%2,%3}, [%4];"
        : "=r"(r[0]), "=r"(r[1]), "=r"(r[2]), "=r"(r[3]) : "r"(a));
}
__device__ __forceinline__ void ldm_x2(u32* r, u32 a) {
    asm volatile("ldmatrix.sync.aligned.m8n8.x2.shared.b16 {%0,%1}, [%2];"
        : "=r"(r[0]), "=r"(r[1]) : "r"(a));
}
__device__ __forceinline__ void ldm_x2t(u32* r, u32 a) {
    asm volatile("ldmatrix.sync.aligned.m8n8.x2.trans.shared.b16 {%0,%1}, [%2];"
        : "=r"(r[0]), "=r"(r[1]) : "r"(a));
}
__device__ __forceinline__ void mma_bf16(float* d, const u32* a, const u32* b) {
    asm volatile(
        "mma.sync.aligned.m16n8k16.row.col.f32.bf16.bf16.f32 "
        "{%0,%1,%2,%3}, {%4,%5,%6,%7}, {%8,%9}, {%0,%1,%2,%3};"
        : "+f"(d[0]), "+f"(d[1]), "+f"(d[2]), "+f"(d[3])
        : "r"(a[0]), "r"(a[1]), "r"(a[2]), "r"(a[3]), "r"(b[0]), "r"(b[1]));
}
__device__ __forceinline__ void mma_f16(float* d, const u32* a, const u32* b) {
    asm volatile(
        "mma.sync.aligned.m16n8k16.row.col.f32.f16.f16.f32 "
        "{%0,%1,%2,%3}, {%4,%5,%6,%7}, {%8,%9}, {%0,%1,%2,%3};"
        : "+f"(d[0]), "+f"(d[1]), "+f"(d[2]), "+f"(d[3])
        : "r"(a[0]), "r"(a[1]), "r"(a[2]), "r"(a[3]), "r"(b[0]), "r"(b[1]));
}

extern __shared__ __align__(16) char dsm[];

// ---------------------------------------------------------------------------
// Converters.
// ---------------------------------------------------------------------------
__device__ __forceinline__ void split4(float4 v, __nv_bfloat16* h, __nv_bfloat16* l, size_t i) {
    __nv_bfloat16 h0 = __float2bfloat16_rn(v.x), h1 = __float2bfloat16_rn(v.y);
    __nv_bfloat16 h2 = __float2bfloat16_rn(v.z), h3 = __float2bfloat16_rn(v.w);
    __nv_bfloat16 l0 = __float2bfloat16_rn(v.x - __bfloat162float(h0));
    __nv_bfloat16 l1 = __float2bfloat16_rn(v.y - __bfloat162float(h1));
    __nv_bfloat16 l2 = __float2bfloat16_rn(v.z - __bfloat162float(h2));
    __nv_bfloat16 l3 = __float2bfloat16_rn(v.w - __bfloat162float(h3));
    *(__nv_bfloat162*)(h + i)     = __nv_bfloat162(h0, h1);
    *(__nv_bfloat162*)(h + i + 2) = __nv_bfloat162(h2, h3);
    *(__nv_bfloat162*)(l + i)     = __nv_bfloat162(l0, l1);
    *(__nv_bfloat162*)(l + i + 2) = __nv_bfloat162(l2, l3);
}

// cam -> single fp16
__global__ __launch_bounds__(256) void k_cvt_cam(const float* __restrict__ src) {
    size_t i = ((size_t)blockIdx.x * 256 + threadIdx.x) * 4;
    float4 v = *(const float4*)(src + i);
    *(__half2*)(g_cam_h + i)     = __half2(__float2half_rn(v.x), __float2half_rn(v.y));
    *(__half2*)(g_cam_h + i + 2) = __half2(__float2half_rn(v.z), __float2half_rn(v.w));
}
__global__ __launch_bounds__(256) void k_cvt_feat(const float* __restrict__ src) {
    size_t i = ((size_t)blockIdx.x * 256 + threadIdx.x) * 4;
    split4(*(const float4*)(src + i), g_feat_h, g_feat_l, i);
}
__global__ __launch_bounds__(256) void k_cvt_w(const float* __restrict__ W1,
                                               const float* __restrict__ W2) {
    size_t i = ((size_t)blockIdx.x * 256 + threadIdx.x) * 4;
    const float* src = (i < (size_t)256 * 2048) ? (W1 + i) : (W2 + i - (size_t)256 * 2048);
    split4(*(const float4*)src, g_Wh, g_Wl, i);
}

// ---------------------------------------------------------------------------
// k_conv_mma (R8 config, unchanged): [f1; f2] = [W1;W2] @ feat. bf16 3-term.
// BM=128, BN=144, K-chunk 32, 2-stage, one barrier per iter.
// ---------------------------------------------------------------------------
#define KC_STAGE 39936

__global__ __launch_bounds__(256) void k_conv_mma() {
    const int tid = threadIdx.x, wid = tid >> 5, l = tid & 31;
    const int b = blockIdx.z, m0 = blockIdx.y * 128, n0 = blockIdx.x * 144;
    const int wm = wid & 3, wn = wid >> 2;
    const u32 smb = smem_u32(dsm);

    const u64 gWh = gaddr(g_Wh), gWl = gaddr(g_Wl);
    const u64 gFh = gaddr(g_feat_h), gFl = gaddr(g_feat_l);

    float acc[2][9][4] = {};

    auto load_tiles = [&](int k0, u32 st) {
        #pragma unroll
        for (int t = 0; t < 9; ++t) {
            const int idx = tid + 256 * t;
            if (idx < 2176) {
                if (idx < 1024) {
                    const int a = idx & 511, r = a >> 2, c = a & 3;
                    const u64 g = ((idx < 512) ? gWh : gWl) +
                        ((u64)(m0 + r) * 2048 + (u32)(k0 + c * 8)) * 2;
                    cp16(st + ((idx < 512) ? 0u : 10240u) + (u32)r * 80 + (u32)c * 16, g);
                } else {
                    const int a2 = idx - 1024;
                    const int half = a2 >= 576;
                    const int j = a2 - (half ? 576 : 0);
                    const int r = j / 18, c = j - r * 18;
                    const u64 g = (half ? gFl : gFh) +
                        ((u64)(b * CH + k0 + r) * NHW + (u32)(n0 + c * 8)) * 2;
                    cp16(st + 20480u + (half ? 9728u : 0u) + (u32)r * 304 + (u32)c * 16, g);
                }
            }
        }
    };

    load_tiles(0, smb);
    CP_COMMIT();

    const u32 a_base = (u32)(wm * 32 + (l & 7) + ((l >> 3) & 1) * 8) * 80 + ((l >> 4) & 1) * 16;
    const int lb = l & 15;
    const u32 b_base = (u32)(((lb >> 3) & 1) * 8 + (lb & 7)) * 304 + (u32)(wn * 72) * 2;

    for (int it = 0; it < 64; ++it) {
        CP_WAIT(0);
        __syncthreads();
        if (it + 1 < 64) {
            load_tiles((it + 1) * 32, smb + (u32)((it + 1) & 1) * KC_STAGE);
            CP_COMMIT();
        }
        const u32 st = smb + (u32)(it & 1) * KC_STAGE;

        #pragma unroll
        for (int k16 = 0; k16 < 2; ++k16) {
            u32 ah[2][4], al[2][4];
            #pragma unroll
            for (int mb = 0; mb < 2; ++mb) {
                ldm_x4(ah[mb], st + a_base + (u32)mb * 1280 + (u32)k16 * 32);
                ldm_x4(al[mb], st + 10240u + a_base + (u32)mb * 1280 + (u32)k16 * 32);
            }
            #pragma unroll
            for (int nb = 0; nb < 9; ++nb) {
                u32 bh[2], bl[2];
                const u32 ba = st + 20480u + b_base + (u32)k16 * (16 * 304) + (u32)nb * 16;
                ldm_x2t(bh, ba);
                ldm_x2t(bl, ba + 9728u);
                #pragma unroll
                for (int mb = 0; mb < 2; ++mb) {
                    mma_bf16(acc[mb][nb], ah[mb], bh);
                    mma_bf16(acc[mb][nb], ah[mb], bl);
                    mma_bf16(acc[mb][nb], al[mb], bh);
                }
            }
        }
    }
    __syncthreads();

    // --- epilogue: smem transpose -> split bf16, write f{1,2}t[n][m] ---
    const int g = l >> 2, t2 = (l & 3) * 2;
    #pragma unroll
    for (int mb = 0; mb < 2; ++mb) {
        #pragma unroll
        for (int nb = 0; nb < 9; ++nb) {
            const int ml = wm * 32 + mb * 16 + g;
            const int nl = wn * 72 + nb * 8 + t2;
            #pragma unroll
            for (int q = 0; q < 4; ++q) {
                const float v = acc[mb][nb][q];
                const int m_ = ml + (q >> 1) * 8;
                const int n_ = nl + (q & 1);
                __nv_bfloat16 h = __float2bfloat16_rn(v);
                __nv_bfloat16 lo = __float2bfloat16_rn(v - __bfloat162float(h));
                *(__nv_bfloat16*)(dsm + (u32)n_ * 256 + (u32)m_ * 2) = h;
                *(__nv_bfloat16*)(dsm + 36864u + (u32)n_ * 256 + (u32)m_ * 2) = lo;
            }
        }
    }
    __syncthreads();

    __nv_bfloat16* dh = (m0 < 256) ? g_f1t_h : g_f2t_h;
    __nv_bfloat16* dl = (m0 < 256) ? g_f1t_l : g_f2t_l;
    const int cb0 = m0 & 255;
    #pragma unroll
    for (int t = 0; t < 9; ++t) {
        const int idx = tid + 256 * t;
        const int j = idx >> 4, c = idx & 15;
        const size_t off = ((size_t)b * NHW + n0 + j) * MID + cb0 + c * 8;
        *(uint4*)(dh + off) = *(const uint4*)(dsm + (u32)j * 256 + (u32)c * 16);
        *(uint4*)(dl + off) = *(const uint4*)(dsm + 36864u + (u32)j * 256 + (u32)c * 16);
    }
}

// ---------------------------------------------------------------------------
// k_logits_mma (unchanged): logits = f1t f2t^T. K=256, bf16 3-term.
// ---------------------------------------------------------------------------
#define KL_STAGE 30720

__global__ __launch_bounds__(256) void k_logits_mma() {
    const int tid = threadIdx.x, wid = tid >> 5, l = tid & 31;
    const int b = blockIdx.z, i0 = blockIdx.y * 96, j0 = blockIdx.x * 96;
    const int wm = wid & 1, wn = wid >> 1;
    const u32 smb = smem_u32(dsm);

    const u64 g1h = gaddr(g_f1t_h), g1l = gaddr(g_f1t_l);
    const u64 g2h = gaddr(g_f2t_h), g2l = gaddr(g_f2t_l);

    float acc[3][3][4] = {};

    auto load_tiles = [&](int k0, u32 st) {
        #pragma unroll
        for (int t = 0; t < 6; ++t) {
            const int idx = tid + 256 * t;
            const int side = idx >= 768;
            const int i2 = idx - (side ? 768 : 0);
            const int half = i2 >= 384;
            const int j2 = i2 - (half ? 384 : 0);
            const int r = j2 >> 2, c = j2 & 3;
            const u64 src = (side ? (half ? g2l : g2h) : (half ? g1l : g1h)) +
                ((u64)(b * NHW + (side ? j0 : i0) + r) * MID + (u32)(k0 + c * 8)) * 2;
            cp16(st + (side ? 15360u : 0u) + (half ? 7680u : 0u) + (u32)r * 80 + (u32)c * 16, src);
        }
    };

    load_tiles(0, smb);
    CP_COMMIT();

    const u32 a_base = (u32)(wm * 48 + (l & 7) + ((l >> 3) & 1) * 8) * 80 + ((l >> 4) & 1) * 16;
    const int lb = l & 15;
    const u32 b_base = (u32)(wn * 24 + (lb & 7)) * 80 + (u32)((lb >> 3) & 1) * 16;

    for (int it = 0; it < 8; ++it) {
        CP_WAIT(0);
        __syncthreads();
        if (it + 1 < 8) {
            load_tiles((it + 1) * 32, smb + (u32)((it + 1) & 1) * KL_STAGE);
            CP_COMMIT();
        }
        const u32 st = smb + (u32)(it & 1) * KL_STAGE;

        #pragma unroll
        for (int k16 = 0; k16 < 2; ++k16) {
            u32 ah[3][4], al[3][4];
            #pragma unroll
            for (int mb = 0; mb < 3; ++mb) {
                ldm_x4(ah[mb], st + a_base + (u32)mb * 1280 + (u32)k16 * 32);
                ldm_x4(al[mb], st + 7680u + a_base + (u32)mb * 1280 + (u32)k16 * 32);
            }
            #pragma unroll
            for (int nb = 0; nb < 3; ++nb) {
                u32 bh[2], bl[2];
                const u32 ba = st + 15360u + b_base + (u32)nb * 640 + (u32)k16 * 32;
                ldm_x2(bh, ba);
                ldm_x2(bl, ba + 7680u);
                #pragma unroll
                for (int mb = 0; mb < 3; ++mb) {
                    mma_bf16(acc[mb][nb], ah[mb], bh);
                    mma_bf16(acc[mb][nb], ah[mb], bl);
                    mma_bf16(acc[mb][nb], al[mb], bh);
                }
            }
        }
    }

    float* ab = g_attn + (size_t)b * NHW * NHW;
    const int g = l >> 2, t2 = (l & 3) * 2;
    #pragma unroll
    for (int mb = 0; mb < 3; ++mb) {
        #pragma unroll
        for (int nb = 0; nb < 3; ++nb) {
            const int row = i0 + wm * 48 + mb * 16 + g;
            const int col = j0 + wn * 24 + nb * 8 + t2;
            const size_t o = (size_t)row * NHW + col;
            *(float2*)(ab + o)           = make_float2(acc[mb][nb][0], acc[mb][nb][1]);
            *(float2*)(ab + o + 8 * NHW) = make_float2(acc[mb][nb][2], acc[mb][nb][3]);
        }
    }
}

// ---------------------------------------------------------------------------
// k_softmax: warp-per-row; emits single fp16 attn.
// ---------------------------------------------------------------------------
__global__ __launch_bounds__(256) void k_softmax() {
    const int wid = threadIdx.x >> 5, l = threadIdx.x & 31;
    const size_t row = (size_t)blockIdx.x * 8 + wid;
    const float* p = g_attn + row * NHW;
    __half* oh = g_attn_fp16 + row * NHW;

    float v[18];
    float m = -1e30f;
    #pragma unroll
    for (int i = 0; i < 18; ++i) { v[i] = p[l + 32 * i]; m = fmaxf(m, v[i]); }
    #pragma unroll
    for (int o = 16; o > 0; o >>= 1) m = fmaxf(m, __shfl_xor_sync(0xffffffffu, m, o));

    float s = 0.f;
    #pragma unroll
    for (int i = 0; i < 18; ++i) { v[i] = __expf(v[i] - m); s += v[i]; }
    #pragma unroll
    for (int o = 16; o > 0; o >>= 1) s += __shfl_xor_sync(0xffffffffu, s, o);

    const float inv = 1.0f / s;
    #pragma unroll
    for (int i = 0; i < 18; ++i) {
        oh[l + 32 * i] = __float2half_rn(v[i] * inv);
    }
}

// ---------------------------------------------------------------------------
// k_out_mma: out = cam + alpha * camh@attn^T  (single fp16 term).
// BM=128, BN=144, warps 4wm x 2wn. K-chunk 32, 2-stage, one barrier/iter.
// stage: Ah(10240) B 144x80 (11520) = 21760. Forced 2 CTAs/SM.
// ---------------------------------------------------------------------------
#define KO_STAGE 21760

__global__ __launch_bounds__(256, 2) void k_out_mma(const float* __restrict__ cam,
                                                    const float* __restrict__ alpha_p,
                                                    float* __restrict__ out) {
    const int tid = threadIdx.x, wid = tid >> 5, l = tid & 31;
    const int b = blockIdx.z, c0 = blockIdx.y * 128, n0 = blockIdx.x * 144;
    const int wm = wid & 3, wn = wid >> 2;
    const u32 smb = smem_u32(dsm);

    const u64 gCh = gaddr(g_cam_h);
    const u64 gA  = gaddr(g_attn_fp16);

    float acc[2][9][4] = {};

    auto load_tiles = [&](int k0, u32 st) {
        #pragma unroll
        for (int t = 0; t < 5; ++t) {
            const int idx = tid + 256 * t;   // used 0..1087
            if (idx < 1088) {
                if (idx < 512) {
                    const int r = idx >> 2, c = idx & 3;
                    const u64 g = gCh +
                        ((u64)(b * CH + c0 + r) * NHW + (u32)(k0 + c * 8)) * 2;
                    cp16(st + (u32)r * 80 + (u32)c * 16, g);
                } else {
                    const int j = idx - 512;       // 0..575
                    const int r = j >> 2, c = j & 3;
                    const u64 g = gA +
                        ((u64)(b * NHW + n0 + r) * NHW + (u32)(k0 + c * 8)) * 2;
                    cp16(st + 10240u + (u32)r * 80 + (u32)c * 16, g);
                }
            }
        }
    };

    load_tiles(0, smb);
    CP_COMMIT();

    const u32 a_base = (u32)(wm * 32 + (l & 7) + ((l >> 3) & 1) * 8) * 80 + ((l >> 4) & 1) * 16;
    const int lb = l & 15;
    const u32 b_base = (u32)(wn * 72 + (lb & 7)) * 80 + (u32)((lb >> 3) & 1) * 16;

    for (int it = 0; it < 18; ++it) {
        CP_WAIT(0);
        __syncthreads();
        if (it + 1 < 18) {
            load_tiles((it + 1) * 32, smb + (u32)((it + 1) & 1) * KO_STAGE);
            CP_COMMIT();
        }
        const u32 st = smb + (u32)(it & 1) * KO_STAGE;

        #pragma unroll
        for (int k16 = 0; k16 < 2; ++k16) {
            u32 ah[2][4];
            #pragma unroll
            for (int mb = 0; mb < 2; ++mb) {
                ldm_x4(ah[mb], st + a_base + (u32)mb * 1280 + (u32)k16 * 32);
            }
            #pragma unroll
            for (int nb = 0; nb < 9; ++nb) {
                u32 bh[2];
                ldm_x2(bh, st + 10240u + b_base + (u32)nb * 640 + (u32)k16 * 32);
                #pragma unroll
                for (int mb = 0; mb < 2; ++mb) {
                    mma_f16(acc[mb][nb], ah[mb], bh);
                }
            }
        }
    }

    const float alpha = *alpha_p;
    const int g = l >> 2, t2 = (l & 3) * 2;
    #pragma unroll
    for (int mb = 0; mb < 2; ++mb) {
        #pragma unroll
        for (int nb = 0; nb < 9; ++nb) {
            const int row = c0 + wm * 32 + mb * 16 + g;
            const int col = n0 + wn * 72 + nb * 8 + t2;
            const size_t o = ((size_t)b * CH + row) * NHW + col;
            float2 cv0 = *(const float2*)(cam + o);
            float2 cv1 = *(const float2*)(cam + o + 8 * NHW);
            *(float2*)(out + o) = make_float2(cv0.x + alpha * acc[mb][nb][0],
                                              cv0.y + alpha * acc[mb][nb][1]);
            *(float2*)(out + o + 8 * NHW) = make_float2(cv1.x + alpha * acc[mb][nb][2],
                                                        cv1.y + alpha * acc[mb][nb][3]);
        }
    }
}

// ---------------------------------------------------------------------------
extern "C" void kernel_launch(void* const* d_in, const int* in_sizes, int n_in,
                              void* d_out, int out_size) {
    const float* cam   = (const float*)d_in[0];
    const float* feat  = (const float*)d_in[1];
    const float* W1    = (const float*)d_in[2];
    const float* W2    = (const float*)d_in[3];
    const float* alpha = (const float*)d_in[4];
    float* out = (float*)d_out;

    cudaFuncSetAttribute(k_conv_mma,   cudaFuncAttributeMaxDynamicSharedMemorySize, 2 * KC_STAGE);
    cudaFuncSetAttribute(k_logits_mma, cudaFuncAttributeMaxDynamicSharedMemorySize, 2 * KL_STAGE);
    cudaFuncSetAttribute(k_out_mma,    cudaFuncAttributeMaxDynamicSharedMemorySize, 2 * KO_STAGE);

    k_cvt_cam<<<36864, 256>>>(cam);
    k_cvt_feat<<<36864, 256>>>(feat);
    k_cvt_w<<<1024, 256>>>(W1, W2);
    k_conv_mma<<<dim3(4, 4, 32), 256, 2 * KC_STAGE>>>();
    k_logits_mma<<<dim3(6, 6, 32), 256, 2 * KL_STAGE>>>();
    k_softmax<<<BATCH * NHW / 8, 256>>>();
    k_out_mma<<<dim3(4, 16, 32), 256, 2 * KO_STAGE>>>(cam, alpha, out);
}

// round 17
// speedup vs baseline: 1.4329x; 1.0034x over previous
#include <cuda_runtime.h>
#include <cuda_bf16.h>
#include <cuda_fp16.h>
#include <cstdint>

#define BATCH 32
#define CH    2048
#define NHW   576
#define MID   256

typedef unsigned long long u64;
typedef uint32_t u32;

// ------------------------- scratch (device globals) -------------------------
__device__ float g_attn[(size_t)BATCH * NHW * NHW];
__device__ __half g_cam_h[(size_t)BATCH * CH * NHW];   // fp16 cam (single limb)
__device__ __nv_bfloat16 g_feat_h[(size_t)BATCH * CH * NHW];
__device__ __nv_bfloat16 g_feat_l[(size_t)BATCH * CH * NHW];
__device__ __half g_attn_fp16[(size_t)BATCH * NHW * NHW];  // single fp16 attn
__device__ __nv_bfloat16 g_Wh[512 * 2048];   // rows 0-255: W1, 256-511: W2
__device__ __nv_bfloat16 g_Wl[512 * 2048];
__device__ __nv_bfloat16 g_f1t_h[(size_t)BATCH * NHW * MID];
__device__ __nv_bfloat16 g_f1t_l[(size_t)BATCH * NHW * MID];
__device__ __nv_bfloat16 g_f2t_h[(size_t)BATCH * NHW * MID];
__device__ __nv_bfloat16 g_f2t_l[(size_t)BATCH * NHW * MID];

// ------------------------- helpers -------------------------
__device__ __forceinline__ u32 smem_u32(const void* p) {
    u32 a;
    asm("{ .reg .u64 t; cvta.to.shared.u64 t, %1; cvt.u32.u64 %0, t; }" : "=r"(a) : "l"(p));
    return a;
}
__device__ __forceinline__ u64 gaddr(const void* p) {
    u64 a; asm("cvta.to.global.u64 %0, %1;" : "=l"(a) : "l"(p)); return a;
}
__device__ __forceinline__ void cp16(u32 s, u64 g) {
    asm volatile("cp.async.cg.shared.global [%0], [%1], 16;" :: "r"(s), "l"(g) : "memory");
}
#define CP_COMMIT() asm volatile("cp.async.commit_group;" ::: "memory")
#define CP_WAIT(n)  asm volatile("cp.async.wait_group %0;" :: "n"(n) : "memory")

__device__ __forceinline__ void ldm_x4(u32* r, u32 a) {
    asm volatile("ldmatrix.sync.aligned.m8n8.x4.shared.b16 {%0,%1,%2,%3}, [%4];"
        : "=r"(r[0]), "=r"(r[1]), "=r"(r[2]), "=r"(r[3]) : "r"(a));
}
__device__ __forceinline__ void ldm_x2(u32* r, u32 a) {
    asm volatile("ldmatrix.sync.aligned.m8n8.x2.shared.b16 {%0,%1}, [%2];"
        : "=r"(r[0]), "=r"(r[1]) : "r"(a));
}
__device__ __forceinline__ void ldm_x2t(u32* r, u32 a) {
    asm volatile("ldmatrix.sync.aligned.m8n8.x2.trans.shared.b16 {%0,%1}, [%2];"
        : "=r"(r[0]), "=r"(r[1]) : "r"(a));
}
__device__ __forceinline__ void mma_bf16(float* d, const u32* a, const u32* b) {
    asm volatile(
        "mma.sync.aligned.m16n8k16.row.col.f32.bf16.bf16.f32 "
        "{%0,%1,%2,%3}, {%4,%5,%6,%7}, {%8,%9}, {%0,%1,%2,%3};"
        : "+f"(d[0]), "+f"(d[1]), "+f"(d[2]), "+f"(d[3])
        : "r"(a[0]), "r"(a[1]), "r"(a[2]), "r"(a[3]), "r"(b[0]), "r"(b[1]));
}
__device__ __forceinline__ void mma_f16(float* d, const u32* a, const u32* b) {
    asm volatile(
        "mma.sync.aligned.m16n8k16.row.col.f32.f16.f16.f32 "
        "{%0,%1,%2,%3}, {%4,%5,%6,%7}, {%8,%9}, {%0,%1,%2,%3};"
        : "+f"(d[0]), "+f"(d[1]), "+f"(d[2]), "+f"(d[3])
        : "r"(a[0]), "r"(a[1]), "r"(a[2]), "r"(a[3]), "r"(b[0]), "r"(b[1]));
}

extern __shared__ __align__(16) char dsm[];

// ---------------------------------------------------------------------------
// Converters.
// ---------------------------------------------------------------------------
__device__ __forceinline__ void split4(float4 v, __nv_bfloat16* h, __nv_bfloat16* l, size_t i) {
    __nv_bfloat16 h0 = __float2bfloat16_rn(v.x), h1 = __float2bfloat16_rn(v.y);
    __nv_bfloat16 h2 = __float2bfloat16_rn(v.z), h3 = __float2bfloat16_rn(v.w);
    __nv_bfloat16 l0 = __float2bfloat16_rn(v.x - __bfloat162float(h0));
    __nv_bfloat16 l1 = __float2bfloat16_rn(v.y - __bfloat162float(h1));
    __nv_bfloat16 l2 = __float2bfloat16_rn(v.z - __bfloat162float(h2));
    __nv_bfloat16 l3 = __float2bfloat16_rn(v.w - __bfloat162float(h3));
    *(__nv_bfloat162*)(h + i)     = __nv_bfloat162(h0, h1);
    *(__nv_bfloat162*)(h + i + 2) = __nv_bfloat162(h2, h3);
    *(__nv_bfloat162*)(l + i)     = __nv_bfloat162(l0, l1);
    *(__nv_bfloat162*)(l + i + 2) = __nv_bfloat162(l2, l3);
}

// fused: cam -> fp16 single limb; feat -> bf16 (hi, lo)
__global__ __launch_bounds__(256) void k_cvt_camfeat(const float* __restrict__ cam,
                                                     const float* __restrict__ feat) {
    size_t i = ((size_t)blockIdx.x * 256 + threadIdx.x) * 4;
    float4 v = *(const float4*)(cam + i);
    *(__half2*)(g_cam_h + i)     = __half2(__float2half_rn(v.x), __float2half_rn(v.y));
    *(__half2*)(g_cam_h + i + 2) = __half2(__float2half_rn(v.z), __float2half_rn(v.w));
    split4(*(const float4*)(feat + i), g_feat_h, g_feat_l, i);
}
__global__ __launch_bounds__(256) void k_cvt_w(const float* __restrict__ W1,
                                               const float* __restrict__ W2) {
    size_t i = ((size_t)blockIdx.x * 256 + threadIdx.x) * 4;
    const float* src = (i < (size_t)256 * 2048) ? (W1 + i) : (W2 + i - (size_t)256 * 2048);
    split4(*(const float4*)src, g_Wh, g_Wl, i);
}

// ---------------------------------------------------------------------------
// k_conv_mma (unchanged): [f1; f2] = [W1;W2] @ feat. bf16 3-term.
// BM=128, BN=144, K-chunk 32, 2-stage, one barrier per iter.
// ---------------------------------------------------------------------------
#define KC_STAGE 39936

__global__ __launch_bounds__(256) void k_conv_mma() {
    const int tid = threadIdx.x, wid = tid >> 5, l = tid & 31;
    const int b = blockIdx.z, m0 = blockIdx.y * 128, n0 = blockIdx.x * 144;
    const int wm = wid & 3, wn = wid >> 2;
    const u32 smb = smem_u32(dsm);

    const u64 gWh = gaddr(g_Wh), gWl = gaddr(g_Wl);
    const u64 gFh = gaddr(g_feat_h), gFl = gaddr(g_feat_l);

    float acc[2][9][4] = {};

    auto load_tiles = [&](int k0, u32 st) {
        #pragma unroll
        for (int t = 0; t < 9; ++t) {
            const int idx = tid + 256 * t;
            if (idx < 2176) {
                if (idx < 1024) {
                    const int a = idx & 511, r = a >> 2, c = a & 3;
                    const u64 g = ((idx < 512) ? gWh : gWl) +
                        ((u64)(m0 + r) * 2048 + (u32)(k0 + c * 8)) * 2;
                    cp16(st + ((idx < 512) ? 0u : 10240u) + (u32)r * 80 + (u32)c * 16, g);
                } else {
                    const int a2 = idx - 1024;
                    const int half = a2 >= 576;
                    const int j = a2 - (half ? 576 : 0);
                    const int r = j / 18, c = j - r * 18;
                    const u64 g = (half ? gFl : gFh) +
                        ((u64)(b * CH + k0 + r) * NHW + (u32)(n0 + c * 8)) * 2;
                    cp16(st + 20480u + (half ? 9728u : 0u) + (u32)r * 304 + (u32)c * 16, g);
                }
            }
        }
    };

    load_tiles(0, smb);
    CP_COMMIT();

    const u32 a_base = (u32)(wm * 32 + (l & 7) + ((l >> 3) & 1) * 8) * 80 + ((l >> 4) & 1) * 16;
    const int lb = l & 15;
    const u32 b_base = (u32)(((lb >> 3) & 1) * 8 + (lb & 7)) * 304 + (u32)(wn * 72) * 2;

    for (int it = 0; it < 64; ++it) {
        CP_WAIT(0);
        __syncthreads();
        if (it + 1 < 64) {
            load_tiles((it + 1) * 32, smb + (u32)((it + 1) & 1) * KC_STAGE);
            CP_COMMIT();
        }
        const u32 st = smb + (u32)(it & 1) * KC_STAGE;

        #pragma unroll
        for (int k16 = 0; k16 < 2; ++k16) {
            u32 ah[2][4], al[2][4];
            #pragma unroll
            for (int mb = 0; mb < 2; ++mb) {
                ldm_x4(ah[mb], st + a_base + (u32)mb * 1280 + (u32)k16 * 32);
                ldm_x4(al[mb], st + 10240u + a_base + (u32)mb * 1280 + (u32)k16 * 32);
            }
            #pragma unroll
            for (int nb = 0; nb < 9; ++nb) {
                u32 bh[2], bl[2];
                const u32 ba = st + 20480u + b_base + (u32)k16 * (16 * 304) + (u32)nb * 16;
                ldm_x2t(bh, ba);
                ldm_x2t(bl, ba + 9728u);
                #pragma unroll
                for (int mb = 0; mb < 2; ++mb) {
                    mma_bf16(acc[mb][nb], ah[mb], bh);
                    mma_bf16(acc[mb][nb], ah[mb], bl);
                    mma_bf16(acc[mb][nb], al[mb], bh);
                }
            }
        }
    }
    __syncthreads();

    // --- epilogue: smem transpose -> split bf16, write f{1,2}t[n][m] ---
    const int g = l >> 2, t2 = (l & 3) * 2;
    #pragma unroll
    for (int mb = 0; mb < 2; ++mb) {
        #pragma unroll
        for (int nb = 0; nb < 9; ++nb) {
            const int ml = wm * 32 + mb * 16 + g;
            const int nl = wn * 72 + nb * 8 + t2;
            #pragma unroll
            for (int q = 0; q < 4; ++q) {
                const float v = acc[mb][nb][q];
                const int m_ = ml + (q >> 1) * 8;
                const int n_ = nl + (q & 1);
                __nv_bfloat16 h = __float2bfloat16_rn(v);
                __nv_bfloat16 lo = __float2bfloat16_rn(v - __bfloat162float(h));
                *(__nv_bfloat16*)(dsm + (u32)n_ * 256 + (u32)m_ * 2) = h;
                *(__nv_bfloat16*)(dsm + 36864u + (u32)n_ * 256 + (u32)m_ * 2) = lo;
            }
        }
    }
    __syncthreads();

    __nv_bfloat16* dh = (m0 < 256) ? g_f1t_h : g_f2t_h;
    __nv_bfloat16* dl = (m0 < 256) ? g_f1t_l : g_f2t_l;
    const int cb0 = m0 & 255;
    #pragma unroll
    for (int t = 0; t < 9; ++t) {
        const int idx = tid + 256 * t;
        const int j = idx >> 4, c = idx & 15;
        const size_t off = ((size_t)b * NHW + n0 + j) * MID + cb0 + c * 8;
        *(uint4*)(dh + off) = *(const uint4*)(dsm + (u32)j * 256 + (u32)c * 16);
        *(uint4*)(dl + off) = *(const uint4*)(dsm + 36864u + (u32)j * 256 + (u32)c * 16);
    }
}

// ---------------------------------------------------------------------------
// k_logits_mma (unchanged): logits = f1t f2t^T. K=256, bf16 3-term.
// ---------------------------------------------------------------------------
#define KL_STAGE 30720

__global__ __launch_bounds__(256) void k_logits_mma() {
    const int tid = threadIdx.x, wid = tid >> 5, l = tid & 31;
    const int b = blockIdx.z, i0 = blockIdx.y * 96, j0 = blockIdx.x * 96;
    const int wm = wid & 1, wn = wid >> 1;
    const u32 smb = smem_u32(dsm);

    const u64 g1h = gaddr(g_f1t_h), g1l = gaddr(g_f1t_l);
    const u64 g2h = gaddr(g_f2t_h), g2l = gaddr(g_f2t_l);

    float acc[3][3][4] = {};

    auto load_tiles = [&](int k0, u32 st) {
        #pragma unroll
        for (int t = 0; t < 6; ++t) {
            const int idx = tid + 256 * t;
            const int side = idx >= 768;
            const int i2 = idx - (side ? 768 : 0);
            const int half = i2 >= 384;
            const int j2 = i2 - (half ? 384 : 0);
            const int r = j2 >> 2, c = j2 & 3;
            const u64 src = (side ? (half ? g2l : g2h) : (half ? g1l : g1h)) +
                ((u64)(b * NHW + (side ? j0 : i0) + r) * MID + (u32)(k0 + c * 8)) * 2;
            cp16(st + (side ? 15360u : 0u) + (half ? 7680u : 0u) + (u32)r * 80 + (u32)c * 16, src);
        }
    };

    load_tiles(0, smb);
    CP_COMMIT();

    const u32 a_base = (u32)(wm * 48 + (l & 7) + ((l >> 3) & 1) * 8) * 80 + ((l >> 4) & 1) * 16;
    const int lb = l & 15;
    const u32 b_base = (u32)(wn * 24 + (lb & 7)) * 80 + (u32)((lb >> 3) & 1) * 16;

    for (int it = 0; it < 8; ++it) {
        CP_WAIT(0);
        __syncthreads();
        if (it + 1 < 8) {
            load_tiles((it + 1) * 32, smb + (u32)((it + 1) & 1) * KL_STAGE);
            CP_COMMIT();
        }
        const u32 st = smb + (u32)(it & 1) * KL_STAGE;

        #pragma unroll
        for (int k16 = 0; k16 < 2; ++k16) {
            u32 ah[3][4], al[3][4];
            #pragma unroll
            for (int mb = 0; mb < 3; ++mb) {
                ldm_x4(ah[mb], st + a_base + (u32)mb * 1280 + (u32)k16 * 32);
                ldm_x4(al[mb], st + 7680u + a_base + (u32)mb * 1280 + (u32)k16 * 32);
            }
            #pragma unroll
            for (int nb = 0; nb < 3; ++nb) {
                u32 bh[2], bl[2];
                const u32 ba = st + 15360u + b_base + (u32)nb * 640 + (u32)k16 * 32;
                ldm_x2(bh, ba);
                ldm_x2(bl, ba + 7680u);
                #pragma unroll
                for (int mb = 0; mb < 3; ++mb) {
                    mma_bf16(acc[mb][nb], ah[mb], bh);
                    mma_bf16(acc[mb][nb], ah[mb], bl);
                    mma_bf16(acc[mb][nb], al[mb], bh);
                }
            }
        }
    }

    float* ab = g_attn + (size_t)b * NHW * NHW;
    const int g = l >> 2, t2 = (l & 3) * 2;
    #pragma unroll
    for (int mb = 0; mb < 3; ++mb) {
        #pragma unroll
        for (int nb = 0; nb < 3; ++nb) {
            const int row = i0 + wm * 48 + mb * 16 + g;
            const int col = j0 + wn * 24 + nb * 8 + t2;
            const size_t o = (size_t)row * NHW + col;
            *(float2*)(ab + o)           = make_float2(acc[mb][nb][0], acc[mb][nb][1]);
            *(float2*)(ab + o + 8 * NHW) = make_float2(acc[mb][nb][2], acc[mb][nb][3]);
        }
    }
}

// ---------------------------------------------------------------------------
// k_softmax: warp-per-row; emits single fp16 attn.
// ---------------------------------------------------------------------------
__global__ __launch_bounds__(256) void k_softmax() {
    const int wid = threadIdx.x >> 5, l = threadIdx.x & 31;
    const size_t row = (size_t)blockIdx.x * 8 + wid;
    const float* p = g_attn + row * NHW;
    __half* oh = g_attn_fp16 + row * NHW;

    float v[18];
    float m = -1e30f;
    #pragma unroll
    for (int i = 0; i < 18; ++i) { v[i] = p[l + 32 * i]; m = fmaxf(m, v[i]); }
    #pragma unroll
    for (int o = 16; o > 0; o >>= 1) m = fmaxf(m, __shfl_xor_sync(0xffffffffu, m, o));

    float s = 0.f;
    #pragma unroll
    for (int i = 0; i < 18; ++i) { v[i] = __expf(v[i] - m); s += v[i]; }
    #pragma unroll
    for (int o = 16; o > 0; o >>= 1) s += __shfl_xor_sync(0xffffffffu, s, o);

    const float inv = 1.0f / s;
    #pragma unroll
    for (int i = 0; i < 18; ++i) {
        oh[l + 32 * i] = __float2half_rn(v[i] * inv);
    }
}

// ---------------------------------------------------------------------------
// k_out_mma: out = cam + alpha * camh@attn^T  (single fp16 term).
// NEW: BM=128, BN=192, warps 2wm (64 rows) x 4wn (48 cols).
// K-chunk 32, 2-stage, one barrier/iter.
// stage: Ah(10240) B 192x80 (15360) = 25600. Forced 2 CTAs/SM.
// ---------------------------------------------------------------------------
#define KO_STAGE 25600

__global__ __launch_bounds__(256, 2) void k_out_mma(const float* __restrict__ cam,
                                                    const float* __restrict__ alpha_p,
                                                    float* __restrict__ out) {
    const int tid = threadIdx.x, wid = tid >> 5, l = tid & 31;
    const int b = blockIdx.z, c0 = blockIdx.y * 128, n0 = blockIdx.x * 192;
    const int wm = wid & 1, wn = wid >> 1;
    const u32 smb = smem_u32(dsm);

    const u64 gCh = gaddr(g_cam_h);
    const u64 gA  = gaddr(g_attn_fp16);

    float acc[4][6][4] = {};

    auto load_tiles = [&](int k0, u32 st) {
        #pragma unroll
        for (int t = 0; t < 5; ++t) {
            const int idx = tid + 256 * t;   // 0..1279
            if (idx < 512) {
                const int r = idx >> 2, c = idx & 3;
                const u64 g = gCh +
                    ((u64)(b * CH + c0 + r) * NHW + (u32)(k0 + c * 8)) * 2;
                cp16(st + (u32)r * 80 + (u32)c * 16, g);
            } else {
                const int j = idx - 512;       // 0..767
                const int r = j >> 2, c = j & 3;
                const u64 g = gA +
                    ((u64)(b * NHW + n0 + r) * NHW + (u32)(k0 + c * 8)) * 2;
                cp16(st + 10240u + (u32)r * 80 + (u32)c * 16, g);
            }
        }
    };

    load_tiles(0, smb);
    CP_COMMIT();

    const u32 a_base = (u32)(wm * 64 + (l & 7) + ((l >> 3) & 1) * 8) * 80 + ((l >> 4) & 1) * 16;
    const int lb = l & 15;
    const u32 b_base = (u32)(wn * 48 + (lb & 7)) * 80 + (u32)((lb >> 3) & 1) * 16;

    for (int it = 0; it < 18; ++it) {
        CP_WAIT(0);
        __syncthreads();
        if (it + 1 < 18) {
            load_tiles((it + 1) * 32, smb + (u32)((it + 1) & 1) * KO_STAGE);
            CP_COMMIT();
        }
        const u32 st = smb + (u32)(it & 1) * KO_STAGE;

        #pragma unroll
        for (int k16 = 0; k16 < 2; ++k16) {
            u32 ah[4][4];
            #pragma unroll
            for (int mb = 0; mb < 4; ++mb) {
                ldm_x4(ah[mb], st + a_base + (u32)mb * 1280 + (u32)k16 * 32);
            }
            #pragma unroll
            for (int nb = 0; nb < 6; ++nb) {
                u32 bh[2];
                ldm_x2(bh, st + 10240u + b_base + (u32)nb * 640 + (u32)k16 * 32);
                #pragma unroll
                for (int mb = 0; mb < 4; ++mb) {
                    mma_f16(acc[mb][nb], ah[mb], bh);
                }
            }
        }
    }

    const float alpha = *alpha_p;
    const int g = l >> 2, t2 = (l & 3) * 2;
    #pragma unroll
    for (int mb = 0; mb < 4; ++mb) {
        #pragma unroll
        for (int nb = 0; nb < 6; ++nb) {
            const int row = c0 + wm * 64 + mb * 16 + g;
            const int col = n0 + wn * 48 + nb * 8 + t2;
            const size_t o = ((size_t)b * CH + row) * NHW + col;
            float2 cv0 = *(const float2*)(cam + o);
            float2 cv1 = *(const float2*)(cam + o + 8 * NHW);
            *(float2*)(out + o) = make_float2(cv0.x + alpha * acc[mb][nb][0],
                                              cv0.y + alpha * acc[mb][nb][1]);
            *(float2*)(out + o + 8 * NHW) = make_float2(cv1.x + alpha * acc[mb][nb][2],
                                                        cv1.y + alpha * acc[mb][nb][3]);
        }
    }
}

// ---------------------------------------------------------------------------
extern "C" void kernel_launch(void* const* d_in, const int* in_sizes, int n_in,
                              void* d_out, int out_size) {
    const float* cam   = (const float*)d_in[0];
    const float* feat  = (const float*)d_in[1];
    const float* W1    = (const float*)d_in[2];
    const float* W2    = (const float*)d_in[3];
    const float* alpha = (const float*)d_in[4];
    float* out = (float*)d_out;

    cudaFuncSetAttribute(k_conv_mma,   cudaFuncAttributeMaxDynamicSharedMemorySize, 2 * KC_STAGE);
    cudaFuncSetAttribute(k_logits_mma, cudaFuncAttributeMaxDynamicSharedMemorySize, 2 * KL_STAGE);
    cudaFuncSetAttribute(k_out_mma,    cudaFuncAttributeMaxDynamicSharedMemorySize, 2 * KO_STAGE);

    k_cvt_camfeat<<<36864, 256>>>(cam, feat);
    k_cvt_w<<<1024, 256>>>(W1, W2);
    k_conv_mma<<<dim3(4, 4, 32), 256, 2 * KC_STAGE>>>();
    k_logits_mma<<<dim3(6, 6, 32), 256, 2 * KL_STAGE>>>();
    k_softmax<<<BATCH * NHW / 8, 256>>>();
    k_out_mma<<<dim3(3, 16, 32), 256, 2 * KO_STAGE>>>(cam, alpha, out);
}